// round 6
// baseline (speedup 1.0000x reference)
#include <cuda_runtime.h>
#include <cuda_fp16.h>
#include <cstdint>

#define N_NODES 50000
#define N_EDGES 1600000
#define IN_DIM 128
#define HID 64
#define NUM_LAYERS 3
#define LN_EPS 1e-5f
#define NCHUNK ((N_NODES + 511) / 512)

// GEMM: 128 rows x 64 cols per block, 256 threads, K processed in 2 phases of 64
#define KC 64
#define STRIDE 72   // halfs per staged row (64 + 8 pad)
#define GEMM_SMEM ((128 * STRIDE * 2 + 64 * STRIDE * 2) * 2)   // 55296 B

// ---------------- scratch (device globals) ----------------------------------
__device__ __half g_hiA[N_NODES * HID];
__device__ __half g_loA[N_NODES * HID];
__device__ __half g_hiB[N_NODES * HID];
__device__ __half g_loB[N_NODES * HID];
__device__ int    g_cnt[N_NODES];
__device__ int    g_excl[N_NODES];
__device__ int    g_row[N_NODES];
__device__ int    g_cur[N_NODES];
__device__ int    g_csum[128];
__device__ float  g_invdeg[N_NODES];
__device__ int    g_esrc[N_EDGES];

__device__ __forceinline__ __half* hibuf(int s) { return s == 0 ? g_hiA : g_hiB; }
__device__ __forceinline__ __half* lobuf(int s) { return s == 0 ? g_loA : g_loB; }

__device__ __forceinline__ uint32_t h2u(__half2 h) {
    return *reinterpret_cast<uint32_t*>(&h);
}
// split 8 fp32 into hi/lo fp16 packs
__device__ __forceinline__ void split8(const float* v, uint4& hi, uint4& lo) {
    __half h[8];
    __half l[8];
#pragma unroll
    for (int i = 0; i < 8; i++) {
        h[i] = __float2half_rn(v[i]);
        l[i] = __float2half_rn(v[i] - __half2float(h[i]));
    }
    hi.x = h2u(__halves2half2(h[0], h[1]));
    hi.y = h2u(__halves2half2(h[2], h[3]));
    hi.z = h2u(__halves2half2(h[4], h[5]));
    hi.w = h2u(__halves2half2(h[6], h[7]));
    lo.x = h2u(__halves2half2(l[0], l[1]));
    lo.y = h2u(__halves2half2(l[2], l[3]));
    lo.z = h2u(__halves2half2(l[4], l[5]));
    lo.w = h2u(__halves2half2(l[6], l[7]));
}

// ---------------- CSR construction -------------------------------------------
__global__ void k_zero_cnt() {
    int i = blockIdx.x * blockDim.x + threadIdx.x;
    if (i < N_NODES) g_cnt[i] = 0;
}

__global__ void k_count(const int* __restrict__ dst) {
    int i = blockIdx.x * blockDim.x + threadIdx.x;
    if (i < N_EDGES / 4) {
        int4 d = ((const int4*)dst)[i];
        atomicAdd(&g_cnt[d.x], 1);
        atomicAdd(&g_cnt[d.y], 1);
        atomicAdd(&g_cnt[d.z], 1);
        atomicAdd(&g_cnt[d.w], 1);
    }
}

__global__ void k_scan1() {
    __shared__ int s[512];
    int c = blockIdx.x, t = threadIdx.x, i = c * 512 + t;
    int v = (i < N_NODES) ? g_cnt[i] : 0;
    s[t] = v;
    __syncthreads();
    for (int off = 1; off < 512; off <<= 1) {
        int x = (t >= off) ? s[t - off] : 0;
        __syncthreads();
        s[t] += x;
        __syncthreads();
    }
    if (i < N_NODES) g_excl[i] = s[t] - v;
    if (t == 511) g_csum[c] = s[511];
}

// finalize: each block redundantly reduces chunk aggregates below it
__global__ void k_scan_fin() {
    __shared__ int s[128];
    int c = blockIdx.x, t = threadIdx.x;
    if (t < 128) s[t] = (t < c && t < NCHUNK) ? g_csum[t] : 0;
    __syncthreads();
    for (int off = 64; off; off >>= 1) {
        if (t < off) s[t] += s[t + off];
        __syncthreads();
    }
    int base = s[0];
    int i = c * 512 + t;
    if (i < N_NODES) {
        int r = base + g_excl[i];
        g_row[i] = r;
        g_cur[i] = r;
        int cc = g_cnt[i];
        g_invdeg[i] = 1.0f / (float)(cc > 0 ? cc : 1);
    }
}

__global__ void k_scatter(const int* __restrict__ src, const int* __restrict__ dst) {
    int i = blockIdx.x * blockDim.x + threadIdx.x;
    if (i < N_EDGES / 4) {
        int4 sv = ((const int4*)src)[i];
        int4 dv = ((const int4*)dst)[i];
        g_esrc[atomicAdd(&g_cur[dv.x], 1)] = sv.x;
        g_esrc[atomicAdd(&g_cur[dv.y], 1)] = sv.y;
        g_esrc[atomicAdd(&g_cur[dv.z], 1)] = sv.z;
        g_esrc[atomicAdd(&g_cur[dv.w], 1)] = sv.w;
    }
}

// ---------------- fused (gather +) split-fp16 HMMA GEMM ----------------------
// out[128n][64j] = A[128n][128k] @ W[64j][128k]^T in two K-phases of 64.
// fc  (xA0 != null): A = xA0 fp32 (split on the fly), B = W0 [64][128] fp32
// layer (xA0 null) : phase0 A = in-kernel CSR mean-gather of h(hsel) (hi path),
//                    phase1 A = h(hsel) hi/lo; B = W0 then W1 ([64][64] each)
// mode: 0 = ReLU -> h(outsel); 1 = LN+ReLU -> h(outsel); 2 = raw -> outF
__global__ void k_gemm(const float* __restrict__ xA0, int hsel,
                       const float* __restrict__ W0, const float* __restrict__ W1,
                       const float* __restrict__ bias,
                       const float* __restrict__ lng, const float* __restrict__ lnbeta,
                       int mode, int outsel, float* __restrict__ outF) {
    extern __shared__ __half sm[];
    __half* sAh = sm;                    // [128][STRIDE]
    __half* sAl = sm + 128 * STRIDE;
    __half* sBh = sm + 256 * STRIDE;     // [64][STRIDE]
    __half* sBl = sm + 320 * STRIDE;

    int t = threadIdx.x;
    int nb = blockIdx.x * 128;
    int warp = t >> 5, lane = t & 31;
    int wm = warp * 16;
    const __half* hHi = hibuf(hsel);
    const __half* hLo = lobuf(hsel);

    float acc[8][4];
#pragma unroll
    for (int p = 0; p < 8; p++)
#pragma unroll
        for (int q = 0; q < 4; q++) acc[p][q] = 0.f;

    // ldmatrix addressing (within a phase tile of KC=64)
    uint32_t aOff = (uint32_t)((wm + (lane & 15)) * STRIDE + (lane >> 4) * 8) * 2;
    uint32_t aShH = (uint32_t)__cvta_generic_to_shared(sAh) + aOff;
    uint32_t aShL = (uint32_t)__cvta_generic_to_shared(sAl) + aOff;
    int ng = lane >> 3;
    int bRow = ((ng >> 1) * 8) + (lane & 7);
    int bK = (ng & 1) * 8;
    uint32_t bShH = (uint32_t)__cvta_generic_to_shared(sBh);
    uint32_t bShL = (uint32_t)__cvta_generic_to_shared(sBl);

#define LDM(r0, r1, r2, r3, addr) \
    asm volatile("ldmatrix.sync.aligned.m8n8.x4.shared.b16 {%0,%1,%2,%3}, [%4];" \
                 : "=r"(r0), "=r"(r1), "=r"(r2), "=r"(r3) : "r"(addr))
#define MMA(accp, x0, x1, x2, x3, y0, y1) \
    asm volatile("mma.sync.aligned.m16n8k16.row.col.f32.f16.f16.f32 " \
                 "{%0,%1,%2,%3}, {%4,%5,%6,%7}, {%8,%9}, {%0,%1,%2,%3};" \
                 : "+f"(accp[0]), "+f"(accp[1]), "+f"(accp[2]), "+f"(accp[3]) \
                 : "r"(x0), "r"(x1), "r"(x2), "r"(x3), "r"(y0), "r"(y1))

#pragma unroll 1
    for (int ph = 0; ph < 2; ph++) {
        // ---- stage B tile for this phase ----
#pragma unroll
        for (int it = 0; it < 2; it++) {
            int idx = it * 256 + t;            // 512 slots
            int j = idx >> 3, k8 = idx & 7;
            float v[8];
            if (xA0) {
                *(float4*)&v[0] = ((const float4*)W0)[j * 32 + ph * 16 + k8 * 2];
                *(float4*)&v[4] = ((const float4*)W0)[j * 32 + ph * 16 + k8 * 2 + 1];
            } else {
                const float* Wp = ph ? W1 : W0;
                *(float4*)&v[0] = ((const float4*)Wp)[j * 16 + k8 * 2];
                *(float4*)&v[4] = ((const float4*)Wp)[j * 16 + k8 * 2 + 1];
            }
            uint4 dh, dl;
            split8(v, dh, dl);
            *(uint4*)&sBh[j * STRIDE + k8 * 8] = dh;
            *(uint4*)&sBl[j * STRIDE + k8 * 8] = dl;
        }

        // ---- stage A tile for this phase ----
        if (!xA0 && ph == 0) {
            // fused CSR mean-gather: warp owns its own 16 MMA rows
            const __half2* hp = (const __half2*)hHi;
#pragma unroll 1
            for (int r = 0; r < 16; r++) {
                int row = wm + r;
                int gn = nb + row;
                float ax = 0.f, ay = 0.f;
                if (gn < N_NODES) {
                    int s = g_row[gn], c = g_cnt[gn];
                    int e = 0;
                    for (; e + 4 <= c; e += 4) {
                        int s0 = g_esrc[s + e + 0];
                        int s1 = g_esrc[s + e + 1];
                        int s2 = g_esrc[s + e + 2];
                        int s3 = g_esrc[s + e + 3];
                        float2 v0 = __half22float2(hp[(size_t)s0 * 32 + lane]);
                        float2 v1 = __half22float2(hp[(size_t)s1 * 32 + lane]);
                        float2 v2 = __half22float2(hp[(size_t)s2 * 32 + lane]);
                        float2 v3 = __half22float2(hp[(size_t)s3 * 32 + lane]);
                        ax += (v0.x + v1.x) + (v2.x + v3.x);
                        ay += (v0.y + v1.y) + (v2.y + v3.y);
                    }
                    for (; e < c; e++) {
                        float2 v0 = __half22float2(hp[(size_t)g_esrc[s + e] * 32 + lane]);
                        ax += v0.x;
                        ay += v0.y;
                    }
                    float id = g_invdeg[gn];
                    ax *= id;
                    ay *= id;
                }
                __half hx = __float2half_rn(ax), hy = __float2half_rn(ay);
                __half lx = __float2half_rn(ax - __half2float(hx));
                __half ly = __float2half_rn(ay - __half2float(hy));
                ((__half2*)&sAh[row * STRIDE])[lane] = __halves2half2(hx, hy);
                ((__half2*)&sAl[row * STRIDE])[lane] = __halves2half2(lx, ly);
            }
        } else {
#pragma unroll
            for (int it = 0; it < 4; it++) {
                int idx = it * 256 + t;        // 1024 slots
                int n = idx >> 3, k8 = idx & 7;
                int gn = nb + n;
                uint4 dh = make_uint4(0u, 0u, 0u, 0u), dl = dh;
                if (gn < N_NODES) {
                    if (xA0) {
                        float v[8];
                        *(float4*)&v[0] = ((const float4*)xA0)[(size_t)gn * 32 + ph * 16 + k8 * 2];
                        *(float4*)&v[4] = ((const float4*)xA0)[(size_t)gn * 32 + ph * 16 + k8 * 2 + 1];
                        split8(v, dh, dl);
                    } else {
                        dh = ((const uint4*)hHi)[(size_t)gn * 8 + k8];
                        dl = ((const uint4*)hLo)[(size_t)gn * 8 + k8];
                    }
                }
                *(uint4*)&sAh[n * STRIDE + k8 * 8] = dh;
                *(uint4*)&sAl[n * STRIDE + k8 * 8] = dl;
            }
        }
        __syncthreads();

        // ---- MMA over this K phase ----
#pragma unroll
        for (int kk = 0; kk < 4; kk++) {
            uint32_t ah0, ah1, ah2, ah3, al0, al1, al2, al3;
            LDM(ah0, ah1, ah2, ah3, aShH + kk * 32);
            LDM(al0, al1, al2, al3, aShL + kk * 32);
#pragma unroll
            for (int tp = 0; tp < 4; tp++) {
                uint32_t bOff = (uint32_t)((tp * 16 + bRow) * STRIDE + kk * 16 + bK) * 2;
                uint32_t bh0, bh1, bh2, bh3, bl0, bl1, bl2, bl3;
                LDM(bh0, bh1, bh2, bh3, bShH + bOff);
                LDM(bl0, bl1, bl2, bl3, bShL + bOff);
                MMA(acc[2 * tp],     ah0, ah1, ah2, ah3, bh0, bh1);
                MMA(acc[2 * tp],     ah0, ah1, ah2, ah3, bl0, bl1);
                MMA(acc[2 * tp],     al0, al1, al2, al3, bh0, bh1);
                MMA(acc[2 * tp + 1], ah0, ah1, ah2, ah3, bh2, bh3);
                MMA(acc[2 * tp + 1], ah0, ah1, ah2, ah3, bl2, bl3);
                MMA(acc[2 * tp + 1], al0, al1, al2, al3, bh2, bh3);
            }
        }
        __syncthreads();
    }
#undef LDM
#undef MMA

    // ---- epilogue: bias (+LN) (+ReLU), write from registers ----
    int r = lane >> 2, cc = (lane & 3) * 2;     // rows wm+r, wm+r+8; cols p*8+cc
#pragma unroll
    for (int p = 0; p < 8; p++) {
        float b0 = __ldg(&bias[p * 8 + cc]);
        float b1 = __ldg(&bias[p * 8 + cc + 1]);
        acc[p][0] += b0; acc[p][1] += b1;
        acc[p][2] += b0; acc[p][3] += b1;
    }
    if (mode == 1) {
        float s0 = 0.f, q0 = 0.f, s1 = 0.f, q1 = 0.f;
#pragma unroll
        for (int p = 0; p < 8; p++) {
            s0 += acc[p][0] + acc[p][1];
            q0 += acc[p][0] * acc[p][0] + acc[p][1] * acc[p][1];
            s1 += acc[p][2] + acc[p][3];
            q1 += acc[p][2] * acc[p][2] + acc[p][3] * acc[p][3];
        }
#pragma unroll
        for (int off = 1; off < 4; off <<= 1) {
            s0 += __shfl_xor_sync(0xffffffffu, s0, off);
            q0 += __shfl_xor_sync(0xffffffffu, q0, off);
            s1 += __shfl_xor_sync(0xffffffffu, s1, off);
            q1 += __shfl_xor_sync(0xffffffffu, q1, off);
        }
        float mu0 = s0 * (1.0f / HID), mu1 = s1 * (1.0f / HID);
        float rs0 = rsqrtf(q0 * (1.0f / HID) - mu0 * mu0 + LN_EPS);
        float rs1 = rsqrtf(q1 * (1.0f / HID) - mu1 * mu1 + LN_EPS);
#pragma unroll
        for (int p = 0; p < 8; p++) {
            float g0 = __ldg(&lng[p * 8 + cc]);
            float g1 = __ldg(&lng[p * 8 + cc + 1]);
            float t0 = __ldg(&lnbeta[p * 8 + cc]);
            float t1 = __ldg(&lnbeta[p * 8 + cc + 1]);
            acc[p][0] = fmaxf(fmaf(g0, (acc[p][0] - mu0) * rs0, t0), 0.f);
            acc[p][1] = fmaxf(fmaf(g1, (acc[p][1] - mu0) * rs0, t1), 0.f);
            acc[p][2] = fmaxf(fmaf(g0, (acc[p][2] - mu1) * rs1, t0), 0.f);
            acc[p][3] = fmaxf(fmaf(g1, (acc[p][3] - mu1) * rs1, t1), 0.f);
        }
    } else if (mode == 0) {
#pragma unroll
        for (int p = 0; p < 8; p++)
#pragma unroll
            for (int q = 0; q < 4; q++) acc[p][q] = fmaxf(acc[p][q], 0.f);
    }

    int gn0 = nb + wm + r, gn1 = gn0 + 8;
    if (mode == 2) {
#pragma unroll
        for (int p = 0; p < 8; p++) {
            int ci = p * 4 + (lane & 3);
            if (gn0 < N_NODES)
                ((float2*)outF)[(size_t)gn0 * 32 + ci] = make_float2(acc[p][0], acc[p][1]);
            if (gn1 < N_NODES)
                ((float2*)outF)[(size_t)gn1 * 32 + ci] = make_float2(acc[p][2], acc[p][3]);
        }
    } else {
        __half2* oHi = (__half2*)hibuf(outsel);
        __half2* oLo = (__half2*)lobuf(outsel);
#pragma unroll
        for (int p = 0; p < 8; p++) {
            int ci = p * 4 + (lane & 3);
            if (gn0 < N_NODES) {
                __half h0 = __float2half_rn(acc[p][0]);
                __half h1 = __float2half_rn(acc[p][1]);
                oHi[(size_t)gn0 * 32 + ci] = __halves2half2(h0, h1);
                oLo[(size_t)gn0 * 32 + ci] = __halves2half2(
                    __float2half_rn(acc[p][0] - __half2float(h0)),
                    __float2half_rn(acc[p][1] - __half2float(h1)));
            }
            if (gn1 < N_NODES) {
                __half h2 = __float2half_rn(acc[p][2]);
                __half h3 = __float2half_rn(acc[p][3]);
                oHi[(size_t)gn1 * 32 + ci] = __halves2half2(h2, h3);
                oLo[(size_t)gn1 * 32 + ci] = __halves2half2(
                    __float2half_rn(acc[p][2] - __half2float(h2)),
                    __float2half_rn(acc[p][3] - __half2float(h3)));
            }
        }
    }
}

// ---------------- launcher ---------------------------------------------------
extern "C" void kernel_launch(void* const* d_in, const int* in_sizes, int n_in,
                              void* d_out, int out_size) {
    const float* x     = (const float*)d_in[0];
    const int*   ei    = (const int*)d_in[1];
    const float* fcW   = (const float*)d_in[3];
    const float* fcb   = (const float*)d_in[4];
    const float* lin_l = (const float*)d_in[5];
    const float* lin_r = (const float*)d_in[6];
    const float* lin_b = (const float*)d_in[7];
    const float* ln_g  = (const float*)d_in[8];
    const float* ln_b  = (const float*)d_in[9];
    const int* src = ei;
    const int* dst = ei + N_EDGES;

    cudaFuncSetAttribute(k_gemm, cudaFuncAttributeMaxDynamicSharedMemorySize, GEMM_SMEM);

    k_zero_cnt<<<(N_NODES + 255) / 256, 256>>>();
    k_count<<<(N_EDGES / 4 + 255) / 256, 256>>>(dst);
    k_scan1<<<NCHUNK, 512>>>();
    k_scan_fin<<<NCHUNK, 512>>>();
    k_scatter<<<(N_EDGES / 4 + 255) / 256, 256>>>(src, dst);

    int gblocks = (N_NODES + 127) / 128;
    // fc: h0 = relu(x @ fcW^T + fcb) -> hi/lo buffer 0
    k_gemm<<<gblocks, 256, GEMM_SMEM>>>(x, 0, fcW, nullptr, fcb,
                                        nullptr, nullptr, 0, 0, nullptr);

    int cur = 0;
    for (int l = 0; l < NUM_LAYERS; l++) {
        int mode = (l < NUM_LAYERS - 1) ? 1 : 2;
        k_gemm<<<gblocks, 256, GEMM_SMEM>>>(nullptr, cur,
                                            lin_l + l * HID * HID,
                                            lin_r + l * HID * HID,
                                            lin_b + l * HID,
                                            ln_g + l * HID, ln_b + l * HID,
                                            mode, 1 - cur, (float*)d_out);
        cur = 1 - cur;
    }
}

// round 8
// speedup vs baseline: 1.3005x; 1.3005x over previous
#include <cuda_runtime.h>
#include <cuda_fp16.h>
#include <cstdint>

#define N_NODES 50000
#define N_EDGES 1600000
#define IN_DIM 128
#define HID 64
#define NUM_LAYERS 3
#define LN_EPS 1e-5f
#define NCHUNK ((N_NODES + 511) / 512)

// GEMM: 128 rows x 64 cols per block, 256 threads, K processed in 2 phases of 64
#define STRIDE 72   // halfs per staged row (64 + 8 pad)
#define GEMM_SMEM ((128 * STRIDE * 2 + 64 * STRIDE * 2) * 2)   // 55296 B

// ---------------- scratch (device globals) ----------------------------------
__device__ __half g_hiA[N_NODES * HID];
__device__ __half g_loA[N_NODES * HID];
__device__ __half g_hiB[N_NODES * HID];
__device__ __half g_loB[N_NODES * HID];
__device__ __half g_aggHi[N_NODES * HID];
__device__ __half g_aggLo[N_NODES * HID];
__device__ int    g_cnt[N_NODES];
__device__ int    g_excl[N_NODES];
__device__ int    g_row[N_NODES];
__device__ int    g_cur[N_NODES];
__device__ int    g_csum[128];
__device__ float  g_invdeg[N_NODES];
__device__ int    g_esrc[N_EDGES];

__device__ __forceinline__ __half* hibuf(int s) { return s == 0 ? g_hiA : g_hiB; }
__device__ __forceinline__ __half* lobuf(int s) { return s == 0 ? g_loA : g_loB; }

__device__ __forceinline__ uint32_t h2u(__half2 h) {
    return *reinterpret_cast<uint32_t*>(&h);
}
// split 8 fp32 into hi/lo fp16 packs
__device__ __forceinline__ void split8(const float* v, uint4& hi, uint4& lo) {
    __half h[8];
    __half l[8];
#pragma unroll
    for (int i = 0; i < 8; i++) {
        h[i] = __float2half_rn(v[i]);
        l[i] = __float2half_rn(v[i] - __half2float(h[i]));
    }
    hi.x = h2u(__halves2half2(h[0], h[1]));
    hi.y = h2u(__halves2half2(h[2], h[3]));
    hi.z = h2u(__halves2half2(h[4], h[5]));
    hi.w = h2u(__halves2half2(h[6], h[7]));
    lo.x = h2u(__halves2half2(l[0], l[1]));
    lo.y = h2u(__halves2half2(l[2], l[3]));
    lo.z = h2u(__halves2half2(l[4], l[5]));
    lo.w = h2u(__halves2half2(l[6], l[7]));
}

// ---------------- CSR construction -------------------------------------------
__global__ void k_zero_cnt() {
    int i = blockIdx.x * blockDim.x + threadIdx.x;
    if (i < N_NODES) g_cnt[i] = 0;
}

__global__ void k_count(const int* __restrict__ dst) {
    int i = blockIdx.x * blockDim.x + threadIdx.x;
    if (i < N_EDGES / 4) {
        int4 d = ((const int4*)dst)[i];
        atomicAdd(&g_cnt[d.x], 1);
        atomicAdd(&g_cnt[d.y], 1);
        atomicAdd(&g_cnt[d.z], 1);
        atomicAdd(&g_cnt[d.w], 1);
    }
}

__global__ void k_scan1() {
    __shared__ int s[512];
    int c = blockIdx.x, t = threadIdx.x, i = c * 512 + t;
    int v = (i < N_NODES) ? g_cnt[i] : 0;
    s[t] = v;
    __syncthreads();
    for (int off = 1; off < 512; off <<= 1) {
        int x = (t >= off) ? s[t - off] : 0;
        __syncthreads();
        s[t] += x;
        __syncthreads();
    }
    if (i < N_NODES) g_excl[i] = s[t] - v;
    if (t == 511) g_csum[c] = s[511];
}

// finalize: each block redundantly reduces chunk aggregates below it
__global__ void k_scan_fin() {
    __shared__ int s[128];
    int c = blockIdx.x, t = threadIdx.x;
    if (t < 128) s[t] = (t < c && t < NCHUNK) ? g_csum[t] : 0;
    __syncthreads();
    for (int off = 64; off; off >>= 1) {
        if (t < off) s[t] += s[t + off];
        __syncthreads();
    }
    int base = s[0];
    int i = c * 512 + t;
    if (i < N_NODES) {
        int r = base + g_excl[i];
        g_row[i] = r;
        g_cur[i] = r;
        int cc = g_cnt[i];
        g_invdeg[i] = 1.0f / (float)(cc > 0 ? cc : 1);
    }
}

__global__ void k_scatter(const int* __restrict__ src, const int* __restrict__ dst) {
    int i = blockIdx.x * blockDim.x + threadIdx.x;
    if (i < N_EDGES / 4) {
        int4 sv = ((const int4*)src)[i];
        int4 dv = ((const int4*)dst)[i];
        g_esrc[atomicAdd(&g_cur[dv.x], 1)] = sv.x;
        g_esrc[atomicAdd(&g_cur[dv.y], 1)] = sv.y;
        g_esrc[atomicAdd(&g_cur[dv.z], 1)] = sv.z;
        g_esrc[atomicAdd(&g_cur[dv.w], 1)] = sv.w;
    }
}

// ---------------- mean aggregation (warp per dst node, fp16-hi gather) -------
__global__ void k_aggregate(int hsel) {
    int gw = (blockIdx.x * blockDim.x + threadIdx.x) >> 5;
    if (gw >= N_NODES) return;
    int lane = threadIdx.x & 31;
    const __half2* hp = (const __half2*)hibuf(hsel);
    int s = g_row[gw], c = g_cnt[gw];
    float ax = 0.f, ay = 0.f;
    int e = 0;
    for (; e + 4 <= c; e += 4) {
        int s0 = g_esrc[s + e + 0];
        int s1 = g_esrc[s + e + 1];
        int s2 = g_esrc[s + e + 2];
        int s3 = g_esrc[s + e + 3];
        float2 v0 = __half22float2(hp[(size_t)s0 * 32 + lane]);
        float2 v1 = __half22float2(hp[(size_t)s1 * 32 + lane]);
        float2 v2 = __half22float2(hp[(size_t)s2 * 32 + lane]);
        float2 v3 = __half22float2(hp[(size_t)s3 * 32 + lane]);
        ax += (v0.x + v1.x) + (v2.x + v3.x);
        ay += (v0.y + v1.y) + (v2.y + v3.y);
    }
    for (; e < c; e++) {
        float2 v0 = __half22float2(hp[(size_t)g_esrc[s + e] * 32 + lane]);
        ax += v0.x;
        ay += v0.y;
    }
    float id = g_invdeg[gw];
    float mx = ax * id, my = ay * id;
    __half hx = __float2half_rn(mx), hy = __float2half_rn(my);
    __half lx = __float2half_rn(mx - __half2float(hx));
    __half ly = __float2half_rn(my - __half2float(hy));
    ((__half2*)g_aggHi)[(size_t)gw * 32 + lane] = __halves2half2(hx, hy);
    ((__half2*)g_aggLo)[(size_t)gw * 32 + lane] = __halves2half2(lx, ly);
}

// ---------------- split-fp16 HMMA GEMM (two K-phases of 64) ------------------
// out[128n][64j] = A[128n][128k] @ W[64j][128k]^T
// fc  (xA0 != null): A = xA0 fp32 (split on the fly), B = W0 [64][128] fp32
// layer (xA0 null) : phase0 A = agg hi/lo, phase1 A = h(hsel) hi/lo;
//                    B = W0 then W1 ([64][64] each)
// mode: 0 = ReLU -> h(outsel); 1 = LN+ReLU -> h(outsel); 2 = raw -> outF
__global__ void k_gemm(const float* __restrict__ xA0, int hsel,
                       const float* __restrict__ W0, const float* __restrict__ W1,
                       const float* __restrict__ bias,
                       const float* __restrict__ lng, const float* __restrict__ lnbeta,
                       int mode, int outsel, float* __restrict__ outF) {
    extern __shared__ __half sm[];
    __half* sAh = sm;                    // [128][STRIDE]
    __half* sAl = sm + 128 * STRIDE;
    __half* sBh = sm + 256 * STRIDE;     // [64][STRIDE]
    __half* sBl = sm + 320 * STRIDE;

    int t = threadIdx.x;
    int nb = blockIdx.x * 128;
    int warp = t >> 5, lane = t & 31;
    int wm = warp * 16;
    const __half* hHi = hibuf(hsel);
    const __half* hLo = lobuf(hsel);

    float acc[8][4];
#pragma unroll
    for (int p = 0; p < 8; p++)
#pragma unroll
        for (int q = 0; q < 4; q++) acc[p][q] = 0.f;

    uint32_t aOff = (uint32_t)((wm + (lane & 15)) * STRIDE + (lane >> 4) * 8) * 2;
    uint32_t aShH = (uint32_t)__cvta_generic_to_shared(sAh) + aOff;
    uint32_t aShL = (uint32_t)__cvta_generic_to_shared(sAl) + aOff;
    int ng = lane >> 3;
    int bRow = ((ng >> 1) * 8) + (lane & 7);
    int bK = (ng & 1) * 8;
    uint32_t bShH = (uint32_t)__cvta_generic_to_shared(sBh);
    uint32_t bShL = (uint32_t)__cvta_generic_to_shared(sBl);

#define LDM(r0, r1, r2, r3, addr) \
    asm volatile("ldmatrix.sync.aligned.m8n8.x4.shared.b16 {%0,%1,%2,%3}, [%4];" \
                 : "=r"(r0), "=r"(r1), "=r"(r2), "=r"(r3) : "r"(addr))
#define MMA(accp, x0, x1, x2, x3, y0, y1) \
    asm volatile("mma.sync.aligned.m16n8k16.row.col.f32.f16.f16.f32 " \
                 "{%0,%1,%2,%3}, {%4,%5,%6,%7}, {%8,%9}, {%0,%1,%2,%3};" \
                 : "+f"(accp[0]), "+f"(accp[1]), "+f"(accp[2]), "+f"(accp[3]) \
                 : "r"(x0), "r"(x1), "r"(x2), "r"(x3), "r"(y0), "r"(y1))

#pragma unroll 1
    for (int ph = 0; ph < 2; ph++) {
        // ---- stage B tile for this phase ----
#pragma unroll
        for (int it = 0; it < 2; it++) {
            int idx = it * 256 + t;            // 512 slots
            int j = idx >> 3, k8 = idx & 7;
            float v[8];
            if (xA0) {
                *(float4*)&v[0] = ((const float4*)W0)[j * 32 + ph * 16 + k8 * 2];
                *(float4*)&v[4] = ((const float4*)W0)[j * 32 + ph * 16 + k8 * 2 + 1];
            } else {
                const float* Wp = ph ? W1 : W0;
                *(float4*)&v[0] = ((const float4*)Wp)[j * 16 + k8 * 2];
                *(float4*)&v[4] = ((const float4*)Wp)[j * 16 + k8 * 2 + 1];
            }
            uint4 dh, dl;
            split8(v, dh, dl);
            *(uint4*)&sBh[j * STRIDE + k8 * 8] = dh;
            *(uint4*)&sBl[j * STRIDE + k8 * 8] = dl;
        }

        // ---- stage A tile for this phase ----
#pragma unroll
        for (int it = 0; it < 4; it++) {
            int idx = it * 256 + t;            // 1024 slots
            int n = idx >> 3, k8 = idx & 7;
            int gn = nb + n;
            uint4 dh = make_uint4(0u, 0u, 0u, 0u), dl = dh;
            if (gn < N_NODES) {
                if (xA0) {
                    float v[8];
                    *(float4*)&v[0] = ((const float4*)xA0)[(size_t)gn * 32 + ph * 16 + k8 * 2];
                    *(float4*)&v[4] = ((const float4*)xA0)[(size_t)gn * 32 + ph * 16 + k8 * 2 + 1];
                    split8(v, dh, dl);
                } else if (ph == 0) {
                    dh = ((const uint4*)g_aggHi)[(size_t)gn * 8 + k8];
                    dl = ((const uint4*)g_aggLo)[(size_t)gn * 8 + k8];
                } else {
                    dh = ((const uint4*)hHi)[(size_t)gn * 8 + k8];
                    dl = ((const uint4*)hLo)[(size_t)gn * 8 + k8];
                }
            }
            *(uint4*)&sAh[n * STRIDE + k8 * 8] = dh;
            *(uint4*)&sAl[n * STRIDE + k8 * 8] = dl;
        }
        __syncthreads();

        // ---- MMA over this K phase ----
#pragma unroll
        for (int kk = 0; kk < 4; kk++) {
            uint32_t ah0, ah1, ah2, ah3, al0, al1, al2, al3;
            LDM(ah0, ah1, ah2, ah3, aShH + kk * 32);
            LDM(al0, al1, al2, al3, aShL + kk * 32);
#pragma unroll
            for (int tp = 0; tp < 4; tp++) {
                uint32_t bOff = (uint32_t)((tp * 16 + bRow) * STRIDE + kk * 16 + bK) * 2;
                uint32_t bh0, bh1, bh2, bh3, bl0, bl1, bl2, bl3;
                LDM(bh0, bh1, bh2, bh3, bShH + bOff);
                LDM(bl0, bl1, bl2, bl3, bShL + bOff);
                MMA(acc[2 * tp],     ah0, ah1, ah2, ah3, bh0, bh1);
                MMA(acc[2 * tp],     ah0, ah1, ah2, ah3, bl0, bl1);
                MMA(acc[2 * tp],     al0, al1, al2, al3, bh0, bh1);
                MMA(acc[2 * tp + 1], ah0, ah1, ah2, ah3, bh2, bh3);
                MMA(acc[2 * tp + 1], ah0, ah1, ah2, ah3, bl2, bl3);
                MMA(acc[2 * tp + 1], al0, al1, al2, al3, bh2, bh3);
            }
        }
        __syncthreads();
    }
#undef LDM
#undef MMA

    // ---- epilogue: bias (+LN) (+ReLU), write from registers ----
    int r = lane >> 2, cc = (lane & 3) * 2;     // rows wm+r, wm+r+8; cols p*8+cc
#pragma unroll
    for (int p = 0; p < 8; p++) {
        float b0 = __ldg(&bias[p * 8 + cc]);
        float b1 = __ldg(&bias[p * 8 + cc + 1]);
        acc[p][0] += b0; acc[p][1] += b1;
        acc[p][2] += b0; acc[p][3] += b1;
    }
    if (mode == 1) {
        float s0 = 0.f, q0 = 0.f, s1 = 0.f, q1 = 0.f;
#pragma unroll
        for (int p = 0; p < 8; p++) {
            s0 += acc[p][0] + acc[p][1];
            q0 += acc[p][0] * acc[p][0] + acc[p][1] * acc[p][1];
            s1 += acc[p][2] + acc[p][3];
            q1 += acc[p][2] * acc[p][2] + acc[p][3] * acc[p][3];
        }
#pragma unroll
        for (int off = 1; off < 4; off <<= 1) {
            s0 += __shfl_xor_sync(0xffffffffu, s0, off);
            q0 += __shfl_xor_sync(0xffffffffu, q0, off);
            s1 += __shfl_xor_sync(0xffffffffu, s1, off);
            q1 += __shfl_xor_sync(0xffffffffu, q1, off);
        }
        float mu0 = s0 * (1.0f / HID), mu1 = s1 * (1.0f / HID);
        float rs0 = rsqrtf(q0 * (1.0f / HID) - mu0 * mu0 + LN_EPS);
        float rs1 = rsqrtf(q1 * (1.0f / HID) - mu1 * mu1 + LN_EPS);
#pragma unroll
        for (int p = 0; p < 8; p++) {
            float g0 = __ldg(&lng[p * 8 + cc]);
            float g1 = __ldg(&lng[p * 8 + cc + 1]);
            float t0 = __ldg(&lnbeta[p * 8 + cc]);
            float t1 = __ldg(&lnbeta[p * 8 + cc + 1]);
            acc[p][0] = fmaxf(fmaf(g0, (acc[p][0] - mu0) * rs0, t0), 0.f);
            acc[p][1] = fmaxf(fmaf(g1, (acc[p][1] - mu0) * rs0, t1), 0.f);
            acc[p][2] = fmaxf(fmaf(g0, (acc[p][2] - mu1) * rs1, t0), 0.f);
            acc[p][3] = fmaxf(fmaf(g1, (acc[p][3] - mu1) * rs1, t1), 0.f);
        }
    } else if (mode == 0) {
#pragma unroll
        for (int p = 0; p < 8; p++)
#pragma unroll
            for (int q = 0; q < 4; q++) acc[p][q] = fmaxf(acc[p][q], 0.f);
    }

    int gn0 = nb + wm + r, gn1 = gn0 + 8;
    if (mode == 2) {
#pragma unroll
        for (int p = 0; p < 8; p++) {
            int ci = p * 4 + (lane & 3);
            if (gn0 < N_NODES)
                ((float2*)outF)[(size_t)gn0 * 32 + ci] = make_float2(acc[p][0], acc[p][1]);
            if (gn1 < N_NODES)
                ((float2*)outF)[(size_t)gn1 * 32 + ci] = make_float2(acc[p][2], acc[p][3]);
        }
    } else {
        __half2* oHi = (__half2*)hibuf(outsel);
        __half2* oLo = (__half2*)lobuf(outsel);
#pragma unroll
        for (int p = 0; p < 8; p++) {
            int ci = p * 4 + (lane & 3);
            if (gn0 < N_NODES) {
                __half h0 = __float2half_rn(acc[p][0]);
                __half h1 = __float2half_rn(acc[p][1]);
                oHi[(size_t)gn0 * 32 + ci] = __halves2half2(h0, h1);
                oLo[(size_t)gn0 * 32 + ci] = __halves2half2(
                    __float2half_rn(acc[p][0] - __half2float(h0)),
                    __float2half_rn(acc[p][1] - __half2float(h1)));
            }
            if (gn1 < N_NODES) {
                __half h2 = __float2half_rn(acc[p][2]);
                __half h3 = __float2half_rn(acc[p][3]);
                oHi[(size_t)gn1 * 32 + ci] = __halves2half2(h2, h3);
                oLo[(size_t)gn1 * 32 + ci] = __halves2half2(
                    __float2half_rn(acc[p][2] - __half2float(h2)),
                    __float2half_rn(acc[p][3] - __half2float(h3)));
            }
        }
    }
}

// ---------------- launcher ---------------------------------------------------
extern "C" void kernel_launch(void* const* d_in, const int* in_sizes, int n_in,
                              void* d_out, int out_size) {
    const float* x     = (const float*)d_in[0];
    const int*   ei    = (const int*)d_in[1];
    const float* fcW   = (const float*)d_in[3];
    const float* fcb   = (const float*)d_in[4];
    const float* lin_l = (const float*)d_in[5];
    const float* lin_r = (const float*)d_in[6];
    const float* lin_b = (const float*)d_in[7];
    const float* ln_g  = (const float*)d_in[8];
    const float* ln_b  = (const float*)d_in[9];
    const int* src = ei;
    const int* dst = ei + N_EDGES;

    cudaFuncSetAttribute(k_gemm, cudaFuncAttributeMaxDynamicSharedMemorySize, GEMM_SMEM);

    k_zero_cnt<<<(N_NODES + 255) / 256, 256>>>();
    k_count<<<(N_EDGES / 4 + 255) / 256, 256>>>(dst);
    k_scan1<<<NCHUNK, 512>>>();
    k_scan_fin<<<NCHUNK, 512>>>();
    k_scatter<<<(N_EDGES / 4 + 255) / 256, 256>>>(src, dst);

    int gblocks = (N_NODES + 127) / 128;
    // fc: h0 = relu(x @ fcW^T + fcb) -> hi/lo buffer 0
    k_gemm<<<gblocks, 256, GEMM_SMEM>>>(x, 0, fcW, nullptr, fcb,
                                        nullptr, nullptr, 0, 0, nullptr);

    int cur = 0;
    for (int l = 0; l < NUM_LAYERS; l++) {
        k_aggregate<<<(N_NODES * 32 + 255) / 256, 256>>>(cur);
        int mode = (l < NUM_LAYERS - 1) ? 1 : 2;
        k_gemm<<<gblocks, 256, GEMM_SMEM>>>(nullptr, cur,
                                            lin_l + l * HID * HID,
                                            lin_r + l * HID * HID,
                                            lin_b + l * HID,
                                            ln_g + l * HID, ln_b + l * HID,
                                            mode, 1 - cur, (float*)d_out);
        cur = 1 - cur;
    }
}

// round 9
// speedup vs baseline: 1.3783x; 1.0598x over previous
#include <cuda_runtime.h>
#include <cuda_fp16.h>
#include <cstdint>

#define N_NODES 50000
#define N_EDGES 1600000
#define IN_DIM 128
#define HID 64
#define NUM_LAYERS 3
#define LN_EPS 1e-5f
#define NCHUNK ((N_NODES + 511) / 512)

// GEMM: 128 rows x 64 cols per block, 256 threads, K processed in 2 phases of 64
#define STRIDE 72   // halfs per staged row (64 + 8 pad)
#define GEMM_SMEM ((128 * STRIDE * 2 + 64 * STRIDE * 2) * 2)   // 55296 B

// ---------------- scratch (device globals) ----------------------------------
__device__ __half g_hiA[N_NODES * HID];
__device__ __half g_loA[N_NODES * HID];
__device__ __half g_hiB[N_NODES * HID];
__device__ __half g_loB[N_NODES * HID];
__device__ __half g_aggHi[N_NODES * HID];
__device__ __half g_aggLo[N_NODES * HID];
__device__ int    g_cnt[N_NODES];
__device__ int    g_excl[N_NODES];
__device__ int    g_row[N_NODES];
__device__ int    g_cur[N_NODES];
__device__ int    g_csum[128];
__device__ float  g_invdeg[N_NODES];
__device__ int    g_esrc[N_EDGES];

__device__ __forceinline__ __half* hibuf(int s) { return s == 0 ? g_hiA : g_hiB; }
__device__ __forceinline__ __half* lobuf(int s) { return s == 0 ? g_loA : g_loB; }

__device__ __forceinline__ uint32_t h2u(__half2 h) {
    return *reinterpret_cast<uint32_t*>(&h);
}
// split 8 fp32 into hi/lo fp16 packs
__device__ __forceinline__ void split8(const float* v, uint4& hi, uint4& lo) {
    __half h[8];
    __half l[8];
#pragma unroll
    for (int i = 0; i < 8; i++) {
        h[i] = __float2half_rn(v[i]);
        l[i] = __float2half_rn(v[i] - __half2float(h[i]));
    }
    hi.x = h2u(__halves2half2(h[0], h[1]));
    hi.y = h2u(__halves2half2(h[2], h[3]));
    hi.z = h2u(__halves2half2(h[4], h[5]));
    hi.w = h2u(__halves2half2(h[6], h[7]));
    lo.x = h2u(__halves2half2(l[0], l[1]));
    lo.y = h2u(__halves2half2(l[2], l[3]));
    lo.z = h2u(__halves2half2(l[4], l[5]));
    lo.w = h2u(__halves2half2(l[6], l[7]));
}

// ---------------- CSR construction -------------------------------------------
__global__ void k_zero_cnt() {
    int i = blockIdx.x * blockDim.x + threadIdx.x;
    if (i < N_NODES) g_cnt[i] = 0;
}

__global__ void k_count(const int* __restrict__ dst) {
    int i = blockIdx.x * blockDim.x + threadIdx.x;
    if (i < N_EDGES / 4) {
        int4 d = ((const int4*)dst)[i];
        atomicAdd(&g_cnt[d.x], 1);
        atomicAdd(&g_cnt[d.y], 1);
        atomicAdd(&g_cnt[d.z], 1);
        atomicAdd(&g_cnt[d.w], 1);
    }
}

__global__ void k_scan1() {
    __shared__ int s[512];
    int c = blockIdx.x, t = threadIdx.x, i = c * 512 + t;
    int v = (i < N_NODES) ? g_cnt[i] : 0;
    s[t] = v;
    __syncthreads();
    for (int off = 1; off < 512; off <<= 1) {
        int x = (t >= off) ? s[t - off] : 0;
        __syncthreads();
        s[t] += x;
        __syncthreads();
    }
    if (i < N_NODES) g_excl[i] = s[t] - v;
    if (t == 511) g_csum[c] = s[511];
}

// finalize: each block redundantly reduces chunk aggregates below it
__global__ void k_scan_fin() {
    __shared__ int s[128];
    int c = blockIdx.x, t = threadIdx.x;
    if (t < 128) s[t] = (t < c && t < NCHUNK) ? g_csum[t] : 0;
    __syncthreads();
    for (int off = 64; off; off >>= 1) {
        if (t < off) s[t] += s[t + off];
        __syncthreads();
    }
    int base = s[0];
    int i = c * 512 + t;
    if (i < N_NODES) {
        int r = base + g_excl[i];
        g_row[i] = r;
        g_cur[i] = r;
        int cc = g_cnt[i];
        g_invdeg[i] = 1.0f / (float)(cc > 0 ? cc : 1);
    }
}

__global__ void k_scatter(const int* __restrict__ src, const int* __restrict__ dst) {
    int i = blockIdx.x * blockDim.x + threadIdx.x;
    if (i < N_EDGES / 4) {
        int4 sv = ((const int4*)src)[i];
        int4 dv = ((const int4*)dst)[i];
        g_esrc[atomicAdd(&g_cur[dv.x], 1)] = sv.x;
        g_esrc[atomicAdd(&g_cur[dv.y], 1)] = sv.y;
        g_esrc[atomicAdd(&g_cur[dv.z], 1)] = sv.z;
        g_esrc[atomicAdd(&g_cur[dv.w], 1)] = sv.w;
    }
}

// ---------------- mean aggregation (warp per dst node) -----------------------
// 8 B per lane: half-warp 0 handles even neighbors, half-warp 1 odd neighbors.
// One LDG.64 warp-instruction covers 2 neighbor rows (256 B).
__global__ void k_aggregate(int hsel) {
    int gw = (blockIdx.x * blockDim.x + threadIdx.x) >> 5;
    if (gw >= N_NODES) return;
    int lane = threadIdx.x & 31;
    int half = lane >> 4;        // 0 = even neighbors, 1 = odd
    int fl = lane & 15;          // covers features [4*fl, 4*fl+4)
    const uint2* hp = (const uint2*)hibuf(hsel);   // 16 uint2 per row
    int s = g_row[gw], c = g_cnt[gw];
    float f0 = 0.f, f1 = 0.f, f2 = 0.f, f3 = 0.f;

    int e = half;
#pragma unroll 1
    for (; e + 6 < c; e += 8) {
        int s0 = g_esrc[s + e + 0];
        int s1 = g_esrc[s + e + 2];
        int s2 = g_esrc[s + e + 4];
        int s3 = g_esrc[s + e + 6];
        uint2 v0 = hp[(size_t)s0 * 16 + fl];
        uint2 v1 = hp[(size_t)s1 * 16 + fl];
        uint2 v2 = hp[(size_t)s2 * 16 + fl];
        uint2 v3 = hp[(size_t)s3 * 16 + fl];
        float2 a0 = __half22float2(*(__half2*)&v0.x), b0 = __half22float2(*(__half2*)&v0.y);
        float2 a1 = __half22float2(*(__half2*)&v1.x), b1 = __half22float2(*(__half2*)&v1.y);
        float2 a2 = __half22float2(*(__half2*)&v2.x), b2 = __half22float2(*(__half2*)&v2.y);
        float2 a3 = __half22float2(*(__half2*)&v3.x), b3 = __half22float2(*(__half2*)&v3.y);
        f0 += (a0.x + a1.x) + (a2.x + a3.x);
        f1 += (a0.y + a1.y) + (a2.y + a3.y);
        f2 += (b0.x + b1.x) + (b2.x + b3.x);
        f3 += (b0.y + b1.y) + (b2.y + b3.y);
    }
    for (; e < c; e += 2) {
        uint2 v0 = hp[(size_t)g_esrc[s + e] * 16 + fl];
        float2 a0 = __half22float2(*(__half2*)&v0.x), b0 = __half22float2(*(__half2*)&v0.y);
        f0 += a0.x;
        f1 += a0.y;
        f2 += b0.x;
        f3 += b0.y;
    }

    // merge even/odd partial sums across half-warps
    f0 += __shfl_xor_sync(0xffffffffu, f0, 16);
    f1 += __shfl_xor_sync(0xffffffffu, f1, 16);
    f2 += __shfl_xor_sync(0xffffffffu, f2, 16);
    f3 += __shfl_xor_sync(0xffffffffu, f3, 16);

    if (half == 0) {
        float id = g_invdeg[gw];
        float m0 = f0 * id, m1 = f1 * id, m2 = f2 * id, m3 = f3 * id;
        __half h0 = __float2half_rn(m0), h1 = __float2half_rn(m1);
        __half h2 = __float2half_rn(m2), h3 = __float2half_rn(m3);
        uint2 dh, dl;
        dh.x = h2u(__halves2half2(h0, h1));
        dh.y = h2u(__halves2half2(h2, h3));
        dl.x = h2u(__halves2half2(__float2half_rn(m0 - __half2float(h0)),
                                  __float2half_rn(m1 - __half2float(h1))));
        dl.y = h2u(__halves2half2(__float2half_rn(m2 - __half2float(h2)),
                                  __float2half_rn(m3 - __half2float(h3))));
        ((uint2*)g_aggHi)[(size_t)gw * 16 + fl] = dh;
        ((uint2*)g_aggLo)[(size_t)gw * 16 + fl] = dl;
    }
}

// ---------------- split-fp16 HMMA GEMM (two K-phases of 64) ------------------
// out[128n][64j] = A[128n][128k] @ W[64j][128k]^T
// fc  (xA0 != null): A = xA0 fp32 (split on the fly), B = W0 [64][128] fp32
// layer (xA0 null) : phase0 A = agg hi/lo, phase1 A = h(hsel) hi/lo;
//                    B = W0 then W1 ([64][64] each)
// mode: 0 = ReLU -> h(outsel); 1 = LN+ReLU -> h(outsel); 2 = raw -> outF
__global__ void k_gemm(const float* __restrict__ xA0, int hsel,
                       const float* __restrict__ W0, const float* __restrict__ W1,
                       const float* __restrict__ bias,
                       const float* __restrict__ lng, const float* __restrict__ lnbeta,
                       int mode, int outsel, float* __restrict__ outF) {
    extern __shared__ __half sm[];
    __half* sAh = sm;                    // [128][STRIDE]
    __half* sAl = sm + 128 * STRIDE;
    __half* sBh = sm + 256 * STRIDE;     // [64][STRIDE]
    __half* sBl = sm + 320 * STRIDE;

    int t = threadIdx.x;
    int nb = blockIdx.x * 128;
    int warp = t >> 5, lane = t & 31;
    int wm = warp * 16;
    const __half* hHi = hibuf(hsel);
    const __half* hLo = lobuf(hsel);

    float acc[8][4];
#pragma unroll
    for (int p = 0; p < 8; p++)
#pragma unroll
        for (int q = 0; q < 4; q++) acc[p][q] = 0.f;

    uint32_t aOff = (uint32_t)((wm + (lane & 15)) * STRIDE + (lane >> 4) * 8) * 2;
    uint32_t aShH = (uint32_t)__cvta_generic_to_shared(sAh) + aOff;
    uint32_t aShL = (uint32_t)__cvta_generic_to_shared(sAl) + aOff;
    int ng = lane >> 3;
    int bRow = ((ng >> 1) * 8) + (lane & 7);
    int bK = (ng & 1) * 8;
    uint32_t bShH = (uint32_t)__cvta_generic_to_shared(sBh);
    uint32_t bShL = (uint32_t)__cvta_generic_to_shared(sBl);

#define LDM(r0, r1, r2, r3, addr) \
    asm volatile("ldmatrix.sync.aligned.m8n8.x4.shared.b16 {%0,%1,%2,%3}, [%4];" \
                 : "=r"(r0), "=r"(r1), "=r"(r2), "=r"(r3) : "r"(addr))
#define MMA(accp, x0, x1, x2, x3, y0, y1) \
    asm volatile("mma.sync.aligned.m16n8k16.row.col.f32.f16.f16.f32 " \
                 "{%0,%1,%2,%3}, {%4,%5,%6,%7}, {%8,%9}, {%0,%1,%2,%3};" \
                 : "+f"(accp[0]), "+f"(accp[1]), "+f"(accp[2]), "+f"(accp[3]) \
                 : "r"(x0), "r"(x1), "r"(x2), "r"(x3), "r"(y0), "r"(y1))

#pragma unroll 1
    for (int ph = 0; ph < 2; ph++) {
        // ---- stage B tile for this phase ----
#pragma unroll
        for (int it = 0; it < 2; it++) {
            int idx = it * 256 + t;            // 512 slots
            int j = idx >> 3, k8 = idx & 7;
            float v[8];
            if (xA0) {
                *(float4*)&v[0] = ((const float4*)W0)[j * 32 + ph * 16 + k8 * 2];
                *(float4*)&v[4] = ((const float4*)W0)[j * 32 + ph * 16 + k8 * 2 + 1];
            } else {
                const float* Wp = ph ? W1 : W0;
                *(float4*)&v[0] = ((const float4*)Wp)[j * 16 + k8 * 2];
                *(float4*)&v[4] = ((const float4*)Wp)[j * 16 + k8 * 2 + 1];
            }
            uint4 dh, dl;
            split8(v, dh, dl);
            *(uint4*)&sBh[j * STRIDE + k8 * 8] = dh;
            *(uint4*)&sBl[j * STRIDE + k8 * 8] = dl;
        }

        // ---- stage A tile for this phase ----
#pragma unroll
        for (int it = 0; it < 4; it++) {
            int idx = it * 256 + t;            // 1024 slots
            int n = idx >> 3, k8 = idx & 7;
            int gn = nb + n;
            uint4 dh = make_uint4(0u, 0u, 0u, 0u), dl = dh;
            if (gn < N_NODES) {
                if (xA0) {
                    float v[8];
                    *(float4*)&v[0] = ((const float4*)xA0)[(size_t)gn * 32 + ph * 16 + k8 * 2];
                    *(float4*)&v[4] = ((const float4*)xA0)[(size_t)gn * 32 + ph * 16 + k8 * 2 + 1];
                    split8(v, dh, dl);
                } else if (ph == 0) {
                    dh = ((const uint4*)g_aggHi)[(size_t)gn * 8 + k8];
                    dl = ((const uint4*)g_aggLo)[(size_t)gn * 8 + k8];
                } else {
                    dh = ((const uint4*)hHi)[(size_t)gn * 8 + k8];
                    dl = ((const uint4*)hLo)[(size_t)gn * 8 + k8];
                }
            }
            *(uint4*)&sAh[n * STRIDE + k8 * 8] = dh;
            *(uint4*)&sAl[n * STRIDE + k8 * 8] = dl;
        }
        __syncthreads();

        // ---- MMA over this K phase ----
#pragma unroll
        for (int kk = 0; kk < 4; kk++) {
            uint32_t ah0, ah1, ah2, ah3, al0, al1, al2, al3;
            LDM(ah0, ah1, ah2, ah3, aShH + kk * 32);
            LDM(al0, al1, al2, al3, aShL + kk * 32);
#pragma unroll
            for (int tp = 0; tp < 4; tp++) {
                uint32_t bOff = (uint32_t)((tp * 16 + bRow) * STRIDE + kk * 16 + bK) * 2;
                uint32_t bh0, bh1, bh2, bh3, bl0, bl1, bl2, bl3;
                LDM(bh0, bh1, bh2, bh3, bShH + bOff);
                LDM(bl0, bl1, bl2, bl3, bShL + bOff);
                MMA(acc[2 * tp],     ah0, ah1, ah2, ah3, bh0, bh1);
                MMA(acc[2 * tp],     ah0, ah1, ah2, ah3, bl0, bl1);
                MMA(acc[2 * tp],     al0, al1, al2, al3, bh0, bh1);
                MMA(acc[2 * tp + 1], ah0, ah1, ah2, ah3, bh2, bh3);
                MMA(acc[2 * tp + 1], ah0, ah1, ah2, ah3, bl2, bl3);
                MMA(acc[2 * tp + 1], al0, al1, al2, al3, bh2, bh3);
            }
        }
        __syncthreads();
    }
#undef LDM
#undef MMA

    // ---- epilogue: bias (+LN) (+ReLU), write from registers ----
    int r = lane >> 2, cc = (lane & 3) * 2;     // rows wm+r, wm+r+8; cols p*8+cc
#pragma unroll
    for (int p = 0; p < 8; p++) {
        float b0 = __ldg(&bias[p * 8 + cc]);
        float b1 = __ldg(&bias[p * 8 + cc + 1]);
        acc[p][0] += b0; acc[p][1] += b1;
        acc[p][2] += b0; acc[p][3] += b1;
    }
    if (mode == 1) {
        float s0 = 0.f, q0 = 0.f, s1 = 0.f, q1 = 0.f;
#pragma unroll
        for (int p = 0; p < 8; p++) {
            s0 += acc[p][0] + acc[p][1];
            q0 += acc[p][0] * acc[p][0] + acc[p][1] * acc[p][1];
            s1 += acc[p][2] + acc[p][3];
            q1 += acc[p][2] * acc[p][2] + acc[p][3] * acc[p][3];
        }
#pragma unroll
        for (int off = 1; off < 4; off <<= 1) {
            s0 += __shfl_xor_sync(0xffffffffu, s0, off);
            q0 += __shfl_xor_sync(0xffffffffu, q0, off);
            s1 += __shfl_xor_sync(0xffffffffu, s1, off);
            q1 += __shfl_xor_sync(0xffffffffu, q1, off);
        }
        float mu0 = s0 * (1.0f / HID), mu1 = s1 * (1.0f / HID);
        float rs0 = rsqrtf(q0 * (1.0f / HID) - mu0 * mu0 + LN_EPS);
        float rs1 = rsqrtf(q1 * (1.0f / HID) - mu1 * mu1 + LN_EPS);
#pragma unroll
        for (int p = 0; p < 8; p++) {
            float g0 = __ldg(&lng[p * 8 + cc]);
            float g1 = __ldg(&lng[p * 8 + cc + 1]);
            float t0 = __ldg(&lnbeta[p * 8 + cc]);
            float t1 = __ldg(&lnbeta[p * 8 + cc + 1]);
            acc[p][0] = fmaxf(fmaf(g0, (acc[p][0] - mu0) * rs0, t0), 0.f);
            acc[p][1] = fmaxf(fmaf(g1, (acc[p][1] - mu0) * rs0, t1), 0.f);
            acc[p][2] = fmaxf(fmaf(g0, (acc[p][2] - mu1) * rs1, t0), 0.f);
            acc[p][3] = fmaxf(fmaf(g1, (acc[p][3] - mu1) * rs1, t1), 0.f);
        }
    } else if (mode == 0) {
#pragma unroll
        for (int p = 0; p < 8; p++)
#pragma unroll
            for (int q = 0; q < 4; q++) acc[p][q] = fmaxf(acc[p][q], 0.f);
    }

    int gn0 = nb + wm + r, gn1 = gn0 + 8;
    if (mode == 2) {
#pragma unroll
        for (int p = 0; p < 8; p++) {
            int ci = p * 4 + (lane & 3);
            if (gn0 < N_NODES)
                ((float2*)outF)[(size_t)gn0 * 32 + ci] = make_float2(acc[p][0], acc[p][1]);
            if (gn1 < N_NODES)
                ((float2*)outF)[(size_t)gn1 * 32 + ci] = make_float2(acc[p][2], acc[p][3]);
        }
    } else {
        __half2* oHi = (__half2*)hibuf(outsel);
        __half2* oLo = (__half2*)lobuf(outsel);
#pragma unroll
        for (int p = 0; p < 8; p++) {
            int ci = p * 4 + (lane & 3);
            if (gn0 < N_NODES) {
                __half h0 = __float2half_rn(acc[p][0]);
                __half h1 = __float2half_rn(acc[p][1]);
                oHi[(size_t)gn0 * 32 + ci] = __halves2half2(h0, h1);
                oLo[(size_t)gn0 * 32 + ci] = __halves2half2(
                    __float2half_rn(acc[p][0] - __half2float(h0)),
                    __float2half_rn(acc[p][1] - __half2float(h1)));
            }
            if (gn1 < N_NODES) {
                __half h2 = __float2half_rn(acc[p][2]);
                __half h3 = __float2half_rn(acc[p][3]);
                oHi[(size_t)gn1 * 32 + ci] = __halves2half2(h2, h3);
                oLo[(size_t)gn1 * 32 + ci] = __halves2half2(
                    __float2half_rn(acc[p][2] - __half2float(h2)),
                    __float2half_rn(acc[p][3] - __half2float(h3)));
            }
        }
    }
}

// ---------------- launcher ---------------------------------------------------
extern "C" void kernel_launch(void* const* d_in, const int* in_sizes, int n_in,
                              void* d_out, int out_size) {
    const float* x     = (const float*)d_in[0];
    const int*   ei    = (const int*)d_in[1];
    const float* fcW   = (const float*)d_in[3];
    const float* fcb   = (const float*)d_in[4];
    const float* lin_l = (const float*)d_in[5];
    const float* lin_r = (const float*)d_in[6];
    const float* lin_b = (const float*)d_in[7];
    const float* ln_g  = (const float*)d_in[8];
    const float* ln_b  = (const float*)d_in[9];
    const int* src = ei;
    const int* dst = ei + N_EDGES;

    cudaFuncSetAttribute(k_gemm, cudaFuncAttributeMaxDynamicSharedMemorySize, GEMM_SMEM);

    k_zero_cnt<<<(N_NODES + 255) / 256, 256>>>();
    k_count<<<(N_EDGES / 4 + 255) / 256, 256>>>(dst);
    k_scan1<<<NCHUNK, 512>>>();
    k_scan_fin<<<NCHUNK, 512>>>();
    k_scatter<<<(N_EDGES / 4 + 255) / 256, 256>>>(src, dst);

    int gblocks = (N_NODES + 127) / 128;
    // fc: h0 = relu(x @ fcW^T + fcb) -> hi/lo buffer 0
    k_gemm<<<gblocks, 256, GEMM_SMEM>>>(x, 0, fcW, nullptr, fcb,
                                        nullptr, nullptr, 0, 0, nullptr);

    int cur = 0;
    for (int l = 0; l < NUM_LAYERS; l++) {
        k_aggregate<<<(N_NODES * 32 + 255) / 256, 256>>>(cur);
        int mode = (l < NUM_LAYERS - 1) ? 1 : 2;
        k_gemm<<<gblocks, 256, GEMM_SMEM>>>(nullptr, cur,
                                            lin_l + l * HID * HID,
                                            lin_r + l * HID * HID,
                                            lin_b + l * HID,
                                            ln_g + l * HID, ln_b + l * HID,
                                            mode, 1 - cur, (float*)d_out);
        cur = 1 - cur;
    }
}

// round 11
// speedup vs baseline: 1.4069x; 1.0208x over previous
#include <cuda_runtime.h>
#include <cuda_fp16.h>
#include <cstdint>

#define N_NODES 50000
#define N_EDGES 1600000
#define IN_DIM 128
#define HID 64
#define NUM_LAYERS 3
#define LN_EPS 1e-5f
#define NCHUNK ((N_NODES + 511) / 512)   // 98

// GEMM: 128 rows x 64 cols per block, 256 threads, K processed in 2 phases of 64
#define STRIDE 72   // halfs per staged row (64 + 8 pad)
#define GEMM_SMEM ((128 * STRIDE * 2 + 64 * STRIDE * 2) * 2)   // 55296 B

// ---------------- scratch (device globals) ----------------------------------
__device__ __half g_hiA[N_NODES * HID];
__device__ __half g_loA[N_NODES * HID];
__device__ __half g_hiB[N_NODES * HID];
__device__ __half g_loB[N_NODES * HID];
__device__ __half g_aggHi[N_NODES * HID];
__device__ __half g_aggLo[N_NODES * HID];
__device__ int    g_cnt[N_NODES];        // zero at entry (zero-init / re-zeroed by final GEMM)
__device__ int    g_excl[N_NODES];
__device__ int    g_row[N_NODES];
__device__ int    g_csum[128];
__device__ float  g_invdeg[N_NODES];
__device__ int    g_rank[N_EDGES];
__device__ int    g_esrc[N_EDGES];

__device__ __forceinline__ __half* hibuf(int s) { return s == 0 ? g_hiA : g_hiB; }
__device__ __forceinline__ __half* lobuf(int s) { return s == 0 ? g_loA : g_loB; }

__device__ __forceinline__ uint32_t h2u(__half2 h) {
    return *reinterpret_cast<uint32_t*>(&h);
}
// split 8 fp32 into hi/lo fp16 packs
__device__ __forceinline__ void split8(const float* v, uint4& hi, uint4& lo) {
    __half h[8];
    __half l[8];
#pragma unroll
    for (int i = 0; i < 8; i++) {
        h[i] = __float2half_rn(v[i]);
        l[i] = __float2half_rn(v[i] - __half2float(h[i]));
    }
    hi.x = h2u(__halves2half2(h[0], h[1]));
    hi.y = h2u(__halves2half2(h[2], h[3]));
    hi.z = h2u(__halves2half2(h[4], h[5]));
    hi.w = h2u(__halves2half2(h[6], h[7]));
    lo.x = h2u(__halves2half2(l[0], l[1]));
    lo.y = h2u(__halves2half2(l[2], l[3]));
    lo.z = h2u(__halves2half2(l[4], l[5]));
    lo.w = h2u(__halves2half2(l[6], l[7]));
}

// ---------------- CSR construction -------------------------------------------
// count: histogram dst AND record each edge's rank within its dst bucket.
__global__ void k_count(const int* __restrict__ dst) {
    int i = blockIdx.x * blockDim.x + threadIdx.x;
    if (i < N_EDGES / 4) {
        int4 d = ((const int4*)dst)[i];
        int4 r;
        r.x = atomicAdd(&g_cnt[d.x], 1);
        r.y = atomicAdd(&g_cnt[d.y], 1);
        r.z = atomicAdd(&g_cnt[d.z], 1);
        r.w = atomicAdd(&g_cnt[d.w], 1);
        ((int4*)g_rank)[i] = r;
    }
}

__global__ void k_scan1() {
    __shared__ int s[512];
    int c = blockIdx.x, t = threadIdx.x, i = c * 512 + t;
    int v = (i < N_NODES) ? g_cnt[i] : 0;
    s[t] = v;
    __syncthreads();
    for (int off = 1; off < 512; off <<= 1) {
        int x = (t >= off) ? s[t - off] : 0;
        __syncthreads();
        s[t] += x;
        __syncthreads();
    }
    if (i < N_NODES) g_excl[i] = s[t] - v;
    if (t == 511) g_csum[c] = s[511];
}

// finalize: each block redundantly reduces chunk aggregates below it
__global__ void k_scan_fin() {
    __shared__ int s[128];
    int c = blockIdx.x, t = threadIdx.x;
    if (t < 128) s[t] = (t < c && t < NCHUNK) ? g_csum[t] : 0;
    __syncthreads();
    for (int off = 64; off; off >>= 1) {
        if (t < off) s[t] += s[t + off];
        __syncthreads();
    }
    int base = s[0];
    int i = c * 512 + t;
    if (i < N_NODES) {
        g_row[i] = base + g_excl[i];
        int cc = g_cnt[i];
        g_invdeg[i] = 1.0f / (float)(cc > 0 ? cc : 1);
    }
}

// scatter with precomputed ranks — no atomics
__global__ void k_scatter(const int* __restrict__ src, const int* __restrict__ dst) {
    int i = blockIdx.x * blockDim.x + threadIdx.x;
    if (i < N_EDGES / 4) {
        int4 sv = ((const int4*)src)[i];
        int4 dv = ((const int4*)dst)[i];
        int4 rv = ((const int4*)g_rank)[i];
        g_esrc[g_row[dv.x] + rv.x] = sv.x;
        g_esrc[g_row[dv.y] + rv.y] = sv.y;
        g_esrc[g_row[dv.z] + rv.z] = sv.z;
        g_esrc[g_row[dv.w] + rv.w] = sv.w;
    }
}

// ---------------- mean aggregation (warp per dst node) -----------------------
// 8 B per lane: half-warp 0 handles even neighbors, half-warp 1 odd neighbors.
__global__ void k_aggregate(int hsel) {
    int gw = (blockIdx.x * blockDim.x + threadIdx.x) >> 5;
    if (gw >= N_NODES) return;
    int lane = threadIdx.x & 31;
    int half = lane >> 4;        // 0 = even neighbors, 1 = odd
    int fl = lane & 15;          // covers features [4*fl, 4*fl+4)
    const uint2* hp = (const uint2*)hibuf(hsel);   // 16 uint2 per row
    int s = g_row[gw], c = g_cnt[gw];
    float f0 = 0.f, f1 = 0.f, f2 = 0.f, f3 = 0.f;

    int e = half;
#pragma unroll 1
    for (; e + 6 < c; e += 8) {
        int s0 = g_esrc[s + e + 0];
        int s1 = g_esrc[s + e + 2];
        int s2 = g_esrc[s + e + 4];
        int s3 = g_esrc[s + e + 6];
        uint2 v0 = hp[(size_t)s0 * 16 + fl];
        uint2 v1 = hp[(size_t)s1 * 16 + fl];
        uint2 v2 = hp[(size_t)s2 * 16 + fl];
        uint2 v3 = hp[(size_t)s3 * 16 + fl];
        float2 a0 = __half22float2(*(__half2*)&v0.x), b0 = __half22float2(*(__half2*)&v0.y);
        float2 a1 = __half22float2(*(__half2*)&v1.x), b1 = __half22float2(*(__half2*)&v1.y);
        float2 a2 = __half22float2(*(__half2*)&v2.x), b2 = __half22float2(*(__half2*)&v2.y);
        float2 a3 = __half22float2(*(__half2*)&v3.x), b3 = __half22float2(*(__half2*)&v3.y);
        f0 += (a0.x + a1.x) + (a2.x + a3.x);
        f1 += (a0.y + a1.y) + (a2.y + a3.y);
        f2 += (b0.x + b1.x) + (b2.x + b3.x);
        f3 += (b0.y + b1.y) + (b2.y + b3.y);
    }
    for (; e < c; e += 2) {
        uint2 v0 = hp[(size_t)g_esrc[s + e] * 16 + fl];
        float2 a0 = __half22float2(*(__half2*)&v0.x), b0 = __half22float2(*(__half2*)&v0.y);
        f0 += a0.x;
        f1 += a0.y;
        f2 += b0.x;
        f3 += b0.y;
    }

    f0 += __shfl_xor_sync(0xffffffffu, f0, 16);
    f1 += __shfl_xor_sync(0xffffffffu, f1, 16);
    f2 += __shfl_xor_sync(0xffffffffu, f2, 16);
    f3 += __shfl_xor_sync(0xffffffffu, f3, 16);

    if (half == 0) {
        float id = g_invdeg[gw];
        float m0 = f0 * id, m1 = f1 * id, m2 = f2 * id, m3 = f3 * id;
        __half h0 = __float2half_rn(m0), h1 = __float2half_rn(m1);
        __half h2 = __float2half_rn(m2), h3 = __float2half_rn(m3);
        uint2 dh, dl;
        dh.x = h2u(__halves2half2(h0, h1));
        dh.y = h2u(__halves2half2(h2, h3));
        dl.x = h2u(__halves2half2(__float2half_rn(m0 - __half2float(h0)),
                                  __float2half_rn(m1 - __half2float(h1))));
        dl.y = h2u(__halves2half2(__float2half_rn(m2 - __half2float(h2)),
                                  __float2half_rn(m3 - __half2float(h3))));
        ((uint2*)g_aggHi)[(size_t)gw * 16 + fl] = dh;
        ((uint2*)g_aggLo)[(size_t)gw * 16 + fl] = dl;
    }
}

// ---------------- split-fp16 HMMA GEMM (two K-phases of 64) ------------------
// mode: 0 = ReLU -> h(outsel); 1 = LN+ReLU -> h(outsel); 2 = raw -> outF (+zero g_cnt)
__global__ void k_gemm(const float* __restrict__ xA0, int hsel,
                       const float* __restrict__ W0, const float* __restrict__ W1,
                       const float* __restrict__ bias,
                       const float* __restrict__ lng, const float* __restrict__ lnbeta,
                       int mode, int outsel, float* __restrict__ outF) {
    extern __shared__ __half sm[];
    __half* sAh = sm;                    // [128][STRIDE]
    __half* sAl = sm + 128 * STRIDE;
    __half* sBh = sm + 256 * STRIDE;     // [64][STRIDE]
    __half* sBl = sm + 320 * STRIDE;

    int t = threadIdx.x;
    int nb = blockIdx.x * 128;
    int warp = t >> 5, lane = t & 31;
    int wm = warp * 16;
    const __half* hHi = hibuf(hsel);
    const __half* hLo = lobuf(hsel);

    float acc[8][4];
#pragma unroll
    for (int p = 0; p < 8; p++)
#pragma unroll
        for (int q = 0; q < 4; q++) acc[p][q] = 0.f;

    uint32_t aOff = (uint32_t)((wm + (lane & 15)) * STRIDE + (lane >> 4) * 8) * 2;
    uint32_t aShH = (uint32_t)__cvta_generic_to_shared(sAh) + aOff;
    uint32_t aShL = (uint32_t)__cvta_generic_to_shared(sAl) + aOff;
    int ng = lane >> 3;
    int bRow = ((ng >> 1) * 8) + (lane & 7);
    int bK = (ng & 1) * 8;
    uint32_t bShH = (uint32_t)__cvta_generic_to_shared(sBh);
    uint32_t bShL = (uint32_t)__cvta_generic_to_shared(sBl);

#define LDM(r0, r1, r2, r3, addr) \
    asm volatile("ldmatrix.sync.aligned.m8n8.x4.shared.b16 {%0,%1,%2,%3}, [%4];" \
                 : "=r"(r0), "=r"(r1), "=r"(r2), "=r"(r3) : "r"(addr))
#define MMA(accp, x0, x1, x2, x3, y0, y1) \
    asm volatile("mma.sync.aligned.m16n8k16.row.col.f32.f16.f16.f32 " \
                 "{%0,%1,%2,%3}, {%4,%5,%6,%7}, {%8,%9}, {%0,%1,%2,%3};" \
                 : "+f"(accp[0]), "+f"(accp[1]), "+f"(accp[2]), "+f"(accp[3]) \
                 : "r"(x0), "r"(x1), "r"(x2), "r"(x3), "r"(y0), "r"(y1))

#pragma unroll 1
    for (int ph = 0; ph < 2; ph++) {
        // ---- stage B tile for this phase ----
#pragma unroll
        for (int it = 0; it < 2; it++) {
            int idx = it * 256 + t;            // 512 slots
            int j = idx >> 3, k8 = idx & 7;
            float v[8];
            if (xA0) {
                *(float4*)&v[0] = ((const float4*)W0)[j * 32 + ph * 16 + k8 * 2];
                *(float4*)&v[4] = ((const float4*)W0)[j * 32 + ph * 16 + k8 * 2 + 1];
            } else {
                const float* Wp = ph ? W1 : W0;
                *(float4*)&v[0] = ((const float4*)Wp)[j * 16 + k8 * 2];
                *(float4*)&v[4] = ((const float4*)Wp)[j * 16 + k8 * 2 + 1];
            }
            uint4 dh, dl;
            split8(v, dh, dl);
            *(uint4*)&sBh[j * STRIDE + k8 * 8] = dh;
            *(uint4*)&sBl[j * STRIDE + k8 * 8] = dl;
        }

        // ---- stage A tile for this phase ----
#pragma unroll
        for (int it = 0; it < 4; it++) {
            int idx = it * 256 + t;            // 1024 slots
            int n = idx >> 3, k8 = idx & 7;
            int gn = nb + n;
            uint4 dh = make_uint4(0u, 0u, 0u, 0u), dl = dh;
            if (gn < N_NODES) {
                if (xA0) {
                    float v[8];
                    *(float4*)&v[0] = ((const float4*)xA0)[(size_t)gn * 32 + ph * 16 + k8 * 2];
                    *(float4*)&v[4] = ((const float4*)xA0)[(size_t)gn * 32 + ph * 16 + k8 * 2 + 1];
                    split8(v, dh, dl);
                } else if (ph == 0) {
                    dh = ((const uint4*)g_aggHi)[(size_t)gn * 8 + k8];
                    dl = ((const uint4*)g_aggLo)[(size_t)gn * 8 + k8];
                } else {
                    dh = ((const uint4*)hHi)[(size_t)gn * 8 + k8];
                    dl = ((const uint4*)hLo)[(size_t)gn * 8 + k8];
                }
            }
            *(uint4*)&sAh[n * STRIDE + k8 * 8] = dh;
            *(uint4*)&sAl[n * STRIDE + k8 * 8] = dl;
        }
        __syncthreads();

        // ---- MMA over this K phase ----
#pragma unroll
        for (int kk = 0; kk < 4; kk++) {
            uint32_t ah0, ah1, ah2, ah3, al0, al1, al2, al3;
            LDM(ah0, ah1, ah2, ah3, aShH + kk * 32);
            LDM(al0, al1, al2, al3, aShL + kk * 32);
#pragma unroll
            for (int tp = 0; tp < 4; tp++) {
                uint32_t bOff = (uint32_t)((tp * 16 + bRow) * STRIDE + kk * 16 + bK) * 2;
                uint32_t bh0, bh1, bh2, bh3, bl0, bl1, bl2, bl3;
                LDM(bh0, bh1, bh2, bh3, bShH + bOff);
                LDM(bl0, bl1, bl2, bl3, bShL + bOff);
                MMA(acc[2 * tp],     ah0, ah1, ah2, ah3, bh0, bh1);
                MMA(acc[2 * tp],     ah0, ah1, ah2, ah3, bl0, bl1);
                MMA(acc[2 * tp],     al0, al1, al2, al3, bh0, bh1);
                MMA(acc[2 * tp + 1], ah0, ah1, ah2, ah3, bh2, bh3);
                MMA(acc[2 * tp + 1], ah0, ah1, ah2, ah3, bl2, bl3);
                MMA(acc[2 * tp + 1], al0, al1, al2, al3, bh2, bh3);
            }
        }
        __syncthreads();
    }
#undef LDM
#undef MMA

    // ---- epilogue: bias (+LN) (+ReLU), write from registers ----
    int r = lane >> 2, cc = (lane & 3) * 2;
#pragma unroll
    for (int p = 0; p < 8; p++) {
        float b0 = __ldg(&bias[p * 8 + cc]);
        float b1 = __ldg(&bias[p * 8 + cc + 1]);
        acc[p][0] += b0; acc[p][1] += b1;
        acc[p][2] += b0; acc[p][3] += b1;
    }
    if (mode == 1) {
        float s0 = 0.f, q0 = 0.f, s1 = 0.f, q1 = 0.f;
#pragma unroll
        for (int p = 0; p < 8; p++) {
            s0 += acc[p][0] + acc[p][1];
            q0 += acc[p][0] * acc[p][0] + acc[p][1] * acc[p][1];
            s1 += acc[p][2] + acc[p][3];
            q1 += acc[p][2] * acc[p][2] + acc[p][3] * acc[p][3];
        }
#pragma unroll
        for (int off = 1; off < 4; off <<= 1) {
            s0 += __shfl_xor_sync(0xffffffffu, s0, off);
            q0 += __shfl_xor_sync(0xffffffffu, q0, off);
            s1 += __shfl_xor_sync(0xffffffffu, s1, off);
            q1 += __shfl_xor_sync(0xffffffffu, q1, off);
        }
        float mu0 = s0 * (1.0f / HID), mu1 = s1 * (1.0f / HID);
        float rs0 = rsqrtf(q0 * (1.0f / HID) - mu0 * mu0 + LN_EPS);
        float rs1 = rsqrtf(q1 * (1.0f / HID) - mu1 * mu1 + LN_EPS);
#pragma unroll
        for (int p = 0; p < 8; p++) {
            float g0 = __ldg(&lng[p * 8 + cc]);
            float g1 = __ldg(&lng[p * 8 + cc + 1]);
            float t0 = __ldg(&lnbeta[p * 8 + cc]);
            float t1 = __ldg(&lnbeta[p * 8 + cc + 1]);
            acc[p][0] = fmaxf(fmaf(g0, (acc[p][0] - mu0) * rs0, t0), 0.f);
            acc[p][1] = fmaxf(fmaf(g1, (acc[p][1] - mu0) * rs0, t1), 0.f);
            acc[p][2] = fmaxf(fmaf(g0, (acc[p][2] - mu1) * rs1, t0), 0.f);
            acc[p][3] = fmaxf(fmaf(g1, (acc[p][3] - mu1) * rs1, t1), 0.f);
        }
    } else if (mode == 0) {
#pragma unroll
        for (int p = 0; p < 8; p++)
#pragma unroll
            for (int q = 0; q < 4; q++) acc[p][q] = fmaxf(acc[p][q], 0.f);
    }

    int gn0 = nb + wm + r, gn1 = gn0 + 8;
    if (mode == 2) {
#pragma unroll
        for (int p = 0; p < 8; p++) {
            int ci = p * 4 + (lane & 3);
            if (gn0 < N_NODES)
                ((float2*)outF)[(size_t)gn0 * 32 + ci] = make_float2(acc[p][0], acc[p][1]);
            if (gn1 < N_NODES)
                ((float2*)outF)[(size_t)gn1 * 32 + ci] = make_float2(acc[p][2], acc[p][3]);
        }
        // restore g_cnt = 0 for the next graph replay (replaces k_zero_cnt)
        if (t < 128) {
            int zi = blockIdx.x * 128 + t;
            if (zi < N_NODES) g_cnt[zi] = 0;
        }
    } else {
        __half2* oHi = (__half2*)hibuf(outsel);
        __half2* oLo = (__half2*)lobuf(outsel);
#pragma unroll
        for (int p = 0; p < 8; p++) {
            int ci = p * 4 + (lane & 3);
            if (gn0 < N_NODES) {
                __half h0 = __float2half_rn(acc[p][0]);
                __half h1 = __float2half_rn(acc[p][1]);
                oHi[(size_t)gn0 * 32 + ci] = __halves2half2(h0, h1);
                oLo[(size_t)gn0 * 32 + ci] = __halves2half2(
                    __float2half_rn(acc[p][0] - __half2float(h0)),
                    __float2half_rn(acc[p][1] - __half2float(h1)));
            }
            if (gn1 < N_NODES) {
                __half h2 = __float2half_rn(acc[p][2]);
                __half h3 = __float2half_rn(acc[p][3]);
                oHi[(size_t)gn1 * 32 + ci] = __halves2half2(h2, h3);
                oLo[(size_t)gn1 * 32 + ci] = __halves2half2(
                    __float2half_rn(acc[p][2] - __half2float(h2)),
                    __float2half_rn(acc[p][3] - __half2float(h3)));
            }
        }
    }
}

// ---------------- launcher ---------------------------------------------------
extern "C" void kernel_launch(void* const* d_in, const int* in_sizes, int n_in,
                              void* d_out, int out_size) {
    const float* x     = (const float*)d_in[0];
    const int*   ei    = (const int*)d_in[1];
    const float* fcW   = (const float*)d_in[3];
    const float* fcb   = (const float*)d_in[4];
    const float* lin_l = (const float*)d_in[5];
    const float* lin_r = (const float*)d_in[6];
    const float* lin_b = (const float*)d_in[7];
    const float* ln_g  = (const float*)d_in[8];
    const float* ln_b  = (const float*)d_in[9];
    const int* src = ei;
    const int* dst = ei + N_EDGES;

    cudaFuncSetAttribute(k_gemm, cudaFuncAttributeMaxDynamicSharedMemorySize, GEMM_SMEM);

    k_count<<<(N_EDGES / 4 + 255) / 256, 256>>>(dst);
    k_scan1<<<NCHUNK, 512>>>();
    k_scan_fin<<<NCHUNK, 512>>>();
    k_scatter<<<(N_EDGES / 4 + 255) / 256, 256>>>(src, dst);

    int gblocks = (N_NODES + 127) / 128;
    // fc: h0 = relu(x @ fcW^T + fcb) -> hi/lo buffer 0
    k_gemm<<<gblocks, 256, GEMM_SMEM>>>(x, 0, fcW, nullptr, fcb,
                                        nullptr, nullptr, 0, 0, nullptr);

    int cur = 0;
    for (int l = 0; l < NUM_LAYERS; l++) {
        k_aggregate<<<(N_NODES * 32 + 255) / 256, 256>>>(cur);
        int mode = (l < NUM_LAYERS - 1) ? 1 : 2;
        k_gemm<<<gblocks, 256, GEMM_SMEM>>>(nullptr, cur,
                                            lin_l + l * HID * HID,
                                            lin_r + l * HID * HID,
                                            lin_b + l * HID,
                                            ln_g + l * HID, ln_b + l * HID,
                                            mode, 1 - cur, (float*)d_out);
        cur = 1 - cur;
    }
}

// round 12
// speedup vs baseline: 1.4674x; 1.0430x over previous
#include <cuda_runtime.h>
#include <cuda_fp16.h>
#include <cstdint>

#define N_NODES 50000
#define N_EDGES 1600000
#define IN_DIM 128
#define HID 64
#define NUM_LAYERS 3
#define LN_EPS 1e-5f
#define NCHUNK ((N_NODES + 511) / 512)   // 98
#define GBLOCKS ((N_NODES + 127) / 128)  // 391
#define CBLOCKS ((N_EDGES / 4 + 255) / 256)  // 1563

// GEMM: 128 rows x 64 cols per block, 256 threads, K processed in 2 phases of 64
#define STRIDE 72   // halfs per staged row (64 + 8 pad)
#define GEMM_SMEM ((128 * STRIDE * 2 + 64 * STRIDE * 2) * 2)   // 55296 B

// ---------------- scratch (device globals) ----------------------------------
__device__ __half g_hiA[N_NODES * HID];
__device__ __half g_loA[N_NODES * HID];
__device__ __half g_hiB[N_NODES * HID];
__device__ __half g_loB[N_NODES * HID];
__device__ __half g_aggHi[N_NODES * HID];
__device__ __half g_aggLo[N_NODES * HID];
__device__ int    g_cnt[N_NODES];        // zero at entry (zero-init / re-zeroed by final GEMM)
__device__ int    g_row[N_NODES];
__device__ float  g_invdeg[N_NODES];
__device__ int    g_rank[N_EDGES];
__device__ int    g_esrc[N_EDGES];

__device__ __forceinline__ __half* hibuf(int s) { return s == 0 ? g_hiA : g_hiB; }
__device__ __forceinline__ __half* lobuf(int s) { return s == 0 ? g_loA : g_loB; }

__device__ __forceinline__ uint32_t h2u(__half2 h) {
    return *reinterpret_cast<uint32_t*>(&h);
}
// split 8 fp32 into hi/lo fp16 packs
__device__ __forceinline__ void split8(const float* v, uint4& hi, uint4& lo) {
    __half h[8];
    __half l[8];
#pragma unroll
    for (int i = 0; i < 8; i++) {
        h[i] = __float2half_rn(v[i]);
        l[i] = __float2half_rn(v[i] - __half2float(h[i]));
    }
    hi.x = h2u(__halves2half2(h[0], h[1]));
    hi.y = h2u(__halves2half2(h[2], h[3]));
    hi.z = h2u(__halves2half2(h[4], h[5]));
    hi.w = h2u(__halves2half2(h[6], h[7]));
    lo.x = h2u(__halves2half2(l[0], l[1]));
    lo.y = h2u(__halves2half2(l[2], l[3]));
    lo.z = h2u(__halves2half2(l[4], l[5]));
    lo.w = h2u(__halves2half2(l[6], l[7]));
}

// ---------------- merged scan: base-reduce + chunk scan ----------------------
__global__ void k_scan() {
    __shared__ int red[512];
    __shared__ int s[512];
    int c = blockIdx.x, t = threadIdx.x, i = c * 512 + t;
    // base = sum g_cnt[0 .. c*512)  (redundant per-block reduce; ~10 MB total)
    int lim = c * 512;
    int acc = 0;
    for (int j = t; j < lim; j += 512) acc += g_cnt[j];
    red[t] = acc;
    __syncthreads();
    for (int off = 256; off; off >>= 1) {
        if (t < off) red[t] += red[t + off];
        __syncthreads();
    }
    int base = red[0];
    int v = (i < N_NODES) ? g_cnt[i] : 0;
    s[t] = v;
    __syncthreads();
    for (int off = 1; off < 512; off <<= 1) {
        int x = (t >= off) ? s[t - off] : 0;
        __syncthreads();
        s[t] += x;
        __syncthreads();
    }
    if (i < N_NODES) {
        g_row[i] = base + s[t] - v;   // exclusive prefix
        g_invdeg[i] = 1.0f / (float)(v > 0 ? v : 1);
    }
}

// scatter with precomputed ranks — no atomics
__global__ void k_scatter(const int* __restrict__ src, const int* __restrict__ dst) {
    int i = blockIdx.x * blockDim.x + threadIdx.x;
    if (i < N_EDGES / 4) {
        int4 sv = ((const int4*)src)[i];
        int4 dv = ((const int4*)dst)[i];
        int4 rv = ((const int4*)g_rank)[i];
        g_esrc[g_row[dv.x] + rv.x] = sv.x;
        g_esrc[g_row[dv.y] + rv.y] = sv.y;
        g_esrc[g_row[dv.z] + rv.z] = sv.z;
        g_esrc[g_row[dv.w] + rv.w] = sv.w;
    }
}

// ---------------- mean aggregation (warp per dst node) -----------------------
// 8 B per lane: half-warp 0 handles even neighbors, half-warp 1 odd neighbors.
__global__ void k_aggregate(int hsel) {
    int gw = (blockIdx.x * blockDim.x + threadIdx.x) >> 5;
    if (gw >= N_NODES) return;
    int lane = threadIdx.x & 31;
    int half = lane >> 4;        // 0 = even neighbors, 1 = odd
    int fl = lane & 15;          // covers features [4*fl, 4*fl+4)
    const uint2* hp = (const uint2*)hibuf(hsel);   // 16 uint2 per row
    int s = g_row[gw], c = g_cnt[gw];
    float f0 = 0.f, f1 = 0.f, f2 = 0.f, f3 = 0.f;

    int e = half;
#pragma unroll 1
    for (; e + 6 < c; e += 8) {
        int s0 = g_esrc[s + e + 0];
        int s1 = g_esrc[s + e + 2];
        int s2 = g_esrc[s + e + 4];
        int s3 = g_esrc[s + e + 6];
        uint2 v0 = hp[(size_t)s0 * 16 + fl];
        uint2 v1 = hp[(size_t)s1 * 16 + fl];
        uint2 v2 = hp[(size_t)s2 * 16 + fl];
        uint2 v3 = hp[(size_t)s3 * 16 + fl];
        float2 a0 = __half22float2(*(__half2*)&v0.x), b0 = __half22float2(*(__half2*)&v0.y);
        float2 a1 = __half22float2(*(__half2*)&v1.x), b1 = __half22float2(*(__half2*)&v1.y);
        float2 a2 = __half22float2(*(__half2*)&v2.x), b2 = __half22float2(*(__half2*)&v2.y);
        float2 a3 = __half22float2(*(__half2*)&v3.x), b3 = __half22float2(*(__half2*)&v3.y);
        f0 += (a0.x + a1.x) + (a2.x + a3.x);
        f1 += (a0.y + a1.y) + (a2.y + a3.y);
        f2 += (b0.x + b1.x) + (b2.x + b3.x);
        f3 += (b0.y + b1.y) + (b2.y + b3.y);
    }
    for (; e < c; e += 2) {
        uint2 v0 = hp[(size_t)g_esrc[s + e] * 16 + fl];
        float2 a0 = __half22float2(*(__half2*)&v0.x), b0 = __half22float2(*(__half2*)&v0.y);
        f0 += a0.x;
        f1 += a0.y;
        f2 += b0.x;
        f3 += b0.y;
    }

    f0 += __shfl_xor_sync(0xffffffffu, f0, 16);
    f1 += __shfl_xor_sync(0xffffffffu, f1, 16);
    f2 += __shfl_xor_sync(0xffffffffu, f2, 16);
    f3 += __shfl_xor_sync(0xffffffffu, f3, 16);

    if (half == 0) {
        float id = g_invdeg[gw];
        float m0 = f0 * id, m1 = f1 * id, m2 = f2 * id, m3 = f3 * id;
        __half h0 = __float2half_rn(m0), h1 = __float2half_rn(m1);
        __half h2 = __float2half_rn(m2), h3 = __float2half_rn(m3);
        uint2 dh, dl;
        dh.x = h2u(__halves2half2(h0, h1));
        dh.y = h2u(__halves2half2(h2, h3));
        dl.x = h2u(__halves2half2(__float2half_rn(m0 - __half2float(h0)),
                                  __float2half_rn(m1 - __half2float(h1))));
        dl.y = h2u(__halves2half2(__float2half_rn(m2 - __half2float(h2)),
                                  __float2half_rn(m3 - __half2float(h3))));
        ((uint2*)g_aggHi)[(size_t)gw * 16 + fl] = dh;
        ((uint2*)g_aggLo)[(size_t)gw * 16 + fl] = dl;
    }
}

// ---------------- split-fp16 HMMA GEMM (two K-phases of 64) ------------------
// mode: 0 = ReLU -> h(outsel); 1 = LN+ReLU -> h(outsel); 2 = raw -> outF (+zero g_cnt)
// dstE non-null (fc call only): blocks >= GBLOCKS run the edge histogram+rank
// (independent of the fc GEMM; overlapped in one launch).
__global__ void k_gemm(const float* __restrict__ xA0, int hsel,
                       const float* __restrict__ W0, const float* __restrict__ W1,
                       const float* __restrict__ bias,
                       const float* __restrict__ lng, const float* __restrict__ lnbeta,
                       int mode, int outsel, float* __restrict__ outF,
                       const int* __restrict__ dstE) {
    if (dstE != nullptr && blockIdx.x >= GBLOCKS) {
        // ---- fused edge count + rank recording ----
        int i = (blockIdx.x - GBLOCKS) * blockDim.x + threadIdx.x;
        if (i < N_EDGES / 4) {
            int4 d = ((const int4*)dstE)[i];
            int4 r;
            r.x = atomicAdd(&g_cnt[d.x], 1);
            r.y = atomicAdd(&g_cnt[d.y], 1);
            r.z = atomicAdd(&g_cnt[d.z], 1);
            r.w = atomicAdd(&g_cnt[d.w], 1);
            ((int4*)g_rank)[i] = r;
        }
        return;
    }

    extern __shared__ __half sm[];
    __half* sAh = sm;                    // [128][STRIDE]
    __half* sAl = sm + 128 * STRIDE;
    __half* sBh = sm + 256 * STRIDE;     // [64][STRIDE]
    __half* sBl = sm + 320 * STRIDE;

    int t = threadIdx.x;
    int nb = blockIdx.x * 128;
    int warp = t >> 5, lane = t & 31;
    int wm = warp * 16;
    const __half* hHi = hibuf(hsel);
    const __half* hLo = lobuf(hsel);

    float acc[8][4];
#pragma unroll
    for (int p = 0; p < 8; p++)
#pragma unroll
        for (int q = 0; q < 4; q++) acc[p][q] = 0.f;

    uint32_t aOff = (uint32_t)((wm + (lane & 15)) * STRIDE + (lane >> 4) * 8) * 2;
    uint32_t aShH = (uint32_t)__cvta_generic_to_shared(sAh) + aOff;
    uint32_t aShL = (uint32_t)__cvta_generic_to_shared(sAl) + aOff;
    int ng = lane >> 3;
    int bRow = ((ng >> 1) * 8) + (lane & 7);
    int bK = (ng & 1) * 8;
    uint32_t bShH = (uint32_t)__cvta_generic_to_shared(sBh);
    uint32_t bShL = (uint32_t)__cvta_generic_to_shared(sBl);

#define LDM(r0, r1, r2, r3, addr) \
    asm volatile("ldmatrix.sync.aligned.m8n8.x4.shared.b16 {%0,%1,%2,%3}, [%4];" \
                 : "=r"(r0), "=r"(r1), "=r"(r2), "=r"(r3) : "r"(addr))
#define MMA(accp, x0, x1, x2, x3, y0, y1) \
    asm volatile("mma.sync.aligned.m16n8k16.row.col.f32.f16.f16.f32 " \
                 "{%0,%1,%2,%3}, {%4,%5,%6,%7}, {%8,%9}, {%0,%1,%2,%3};" \
                 : "+f"(accp[0]), "+f"(accp[1]), "+f"(accp[2]), "+f"(accp[3]) \
                 : "r"(x0), "r"(x1), "r"(x2), "r"(x3), "r"(y0), "r"(y1))

#pragma unroll 1
    for (int ph = 0; ph < 2; ph++) {
        // ---- stage B tile for this phase ----
#pragma unroll
        for (int it = 0; it < 2; it++) {
            int idx = it * 256 + t;            // 512 slots
            int j = idx >> 3, k8 = idx & 7;
            float v[8];
            if (xA0) {
                *(float4*)&v[0] = ((const float4*)W0)[j * 32 + ph * 16 + k8 * 2];
                *(float4*)&v[4] = ((const float4*)W0)[j * 32 + ph * 16 + k8 * 2 + 1];
            } else {
                const float* Wp = ph ? W1 : W0;
                *(float4*)&v[0] = ((const float4*)Wp)[j * 16 + k8 * 2];
                *(float4*)&v[4] = ((const float4*)Wp)[j * 16 + k8 * 2 + 1];
            }
            uint4 dh, dl;
            split8(v, dh, dl);
            *(uint4*)&sBh[j * STRIDE + k8 * 8] = dh;
            *(uint4*)&sBl[j * STRIDE + k8 * 8] = dl;
        }

        // ---- stage A tile for this phase ----
#pragma unroll
        for (int it = 0; it < 4; it++) {
            int idx = it * 256 + t;            // 1024 slots
            int n = idx >> 3, k8 = idx & 7;
            int gn = nb + n;
            uint4 dh = make_uint4(0u, 0u, 0u, 0u), dl = dh;
            if (gn < N_NODES) {
                if (xA0) {
                    float v[8];
                    *(float4*)&v[0] = ((const float4*)xA0)[(size_t)gn * 32 + ph * 16 + k8 * 2];
                    *(float4*)&v[4] = ((const float4*)xA0)[(size_t)gn * 32 + ph * 16 + k8 * 2 + 1];
                    split8(v, dh, dl);
                } else if (ph == 0) {
                    dh = ((const uint4*)g_aggHi)[(size_t)gn * 8 + k8];
                    dl = ((const uint4*)g_aggLo)[(size_t)gn * 8 + k8];
                } else {
                    dh = ((const uint4*)hHi)[(size_t)gn * 8 + k8];
                    dl = ((const uint4*)hLo)[(size_t)gn * 8 + k8];
                }
            }
            *(uint4*)&sAh[n * STRIDE + k8 * 8] = dh;
            *(uint4*)&sAl[n * STRIDE + k8 * 8] = dl;
        }
        __syncthreads();

        // ---- MMA over this K phase ----
#pragma unroll
        for (int kk = 0; kk < 4; kk++) {
            uint32_t ah0, ah1, ah2, ah3, al0, al1, al2, al3;
            LDM(ah0, ah1, ah2, ah3, aShH + kk * 32);
            LDM(al0, al1, al2, al3, aShL + kk * 32);
#pragma unroll
            for (int tp = 0; tp < 4; tp++) {
                uint32_t bOff = (uint32_t)((tp * 16 + bRow) * STRIDE + kk * 16 + bK) * 2;
                uint32_t bh0, bh1, bh2, bh3, bl0, bl1, bl2, bl3;
                LDM(bh0, bh1, bh2, bh3, bShH + bOff);
                LDM(bl0, bl1, bl2, bl3, bShL + bOff);
                MMA(acc[2 * tp],     ah0, ah1, ah2, ah3, bh0, bh1);
                MMA(acc[2 * tp],     ah0, ah1, ah2, ah3, bl0, bl1);
                MMA(acc[2 * tp],     al0, al1, al2, al3, bh0, bh1);
                MMA(acc[2 * tp + 1], ah0, ah1, ah2, ah3, bh2, bh3);
                MMA(acc[2 * tp + 1], ah0, ah1, ah2, ah3, bl2, bl3);
                MMA(acc[2 * tp + 1], al0, al1, al2, al3, bh2, bh3);
            }
        }
        __syncthreads();
    }
#undef LDM
#undef MMA

    // ---- epilogue: bias (+LN) (+ReLU), write from registers ----
    int r = lane >> 2, cc = (lane & 3) * 2;
#pragma unroll
    for (int p = 0; p < 8; p++) {
        float b0 = __ldg(&bias[p * 8 + cc]);
        float b1 = __ldg(&bias[p * 8 + cc + 1]);
        acc[p][0] += b0; acc[p][1] += b1;
        acc[p][2] += b0; acc[p][3] += b1;
    }
    if (mode == 1) {
        float s0 = 0.f, q0 = 0.f, s1 = 0.f, q1 = 0.f;
#pragma unroll
        for (int p = 0; p < 8; p++) {
            s0 += acc[p][0] + acc[p][1];
            q0 += acc[p][0] * acc[p][0] + acc[p][1] * acc[p][1];
            s1 += acc[p][2] + acc[p][3];
            q1 += acc[p][2] * acc[p][2] + acc[p][3] * acc[p][3];
        }
#pragma unroll
        for (int off = 1; off < 4; off <<= 1) {
            s0 += __shfl_xor_sync(0xffffffffu, s0, off);
            q0 += __shfl_xor_sync(0xffffffffu, q0, off);
            s1 += __shfl_xor_sync(0xffffffffu, s1, off);
            q1 += __shfl_xor_sync(0xffffffffu, q1, off);
        }
        float mu0 = s0 * (1.0f / HID), mu1 = s1 * (1.0f / HID);
        float rs0 = rsqrtf(q0 * (1.0f / HID) - mu0 * mu0 + LN_EPS);
        float rs1 = rsqrtf(q1 * (1.0f / HID) - mu1 * mu1 + LN_EPS);
#pragma unroll
        for (int p = 0; p < 8; p++) {
            float g0 = __ldg(&lng[p * 8 + cc]);
            float g1 = __ldg(&lng[p * 8 + cc + 1]);
            float t0 = __ldg(&lnbeta[p * 8 + cc]);
            float t1 = __ldg(&lnbeta[p * 8 + cc + 1]);
            acc[p][0] = fmaxf(fmaf(g0, (acc[p][0] - mu0) * rs0, t0), 0.f);
            acc[p][1] = fmaxf(fmaf(g1, (acc[p][1] - mu0) * rs0, t1), 0.f);
            acc[p][2] = fmaxf(fmaf(g0, (acc[p][2] - mu1) * rs1, t0), 0.f);
            acc[p][3] = fmaxf(fmaf(g1, (acc[p][3] - mu1) * rs1, t1), 0.f);
        }
    } else if (mode == 0) {
#pragma unroll
        for (int p = 0; p < 8; p++)
#pragma unroll
            for (int q = 0; q < 4; q++) acc[p][q] = fmaxf(acc[p][q], 0.f);
    }

    int gn0 = nb + wm + r, gn1 = gn0 + 8;
    if (mode == 2) {
#pragma unroll
        for (int p = 0; p < 8; p++) {
            int ci = p * 4 + (lane & 3);
            if (gn0 < N_NODES)
                ((float2*)outF)[(size_t)gn0 * 32 + ci] = make_float2(acc[p][0], acc[p][1]);
            if (gn1 < N_NODES)
                ((float2*)outF)[(size_t)gn1 * 32 + ci] = make_float2(acc[p][2], acc[p][3]);
        }
        // restore g_cnt = 0 for the next graph replay
        if (t < 128) {
            int zi = blockIdx.x * 128 + t;
            if (zi < N_NODES) g_cnt[zi] = 0;
        }
    } else {
        __half2* oHi = (__half2*)hibuf(outsel);
        __half2* oLo = (__half2*)lobuf(outsel);
#pragma unroll
        for (int p = 0; p < 8; p++) {
            int ci = p * 4 + (lane & 3);
            if (gn0 < N_NODES) {
                __half h0 = __float2half_rn(acc[p][0]);
                __half h1 = __float2half_rn(acc[p][1]);
                oHi[(size_t)gn0 * 32 + ci] = __halves2half2(h0, h1);
                oLo[(size_t)gn0 * 32 + ci] = __halves2half2(
                    __float2half_rn(acc[p][0] - __half2float(h0)),
                    __float2half_rn(acc[p][1] - __half2float(h1)));
            }
            if (gn1 < N_NODES) {
                __half h2 = __float2half_rn(acc[p][2]);
                __half h3 = __float2half_rn(acc[p][3]);
                oHi[(size_t)gn1 * 32 + ci] = __halves2half2(h2, h3);
                oLo[(size_t)gn1 * 32 + ci] = __halves2half2(
                    __float2half_rn(acc[p][2] - __half2float(h2)),
                    __float2half_rn(acc[p][3] - __half2float(h3)));
            }
        }
    }
}

// ---------------- launcher ---------------------------------------------------
extern "C" void kernel_launch(void* const* d_in, const int* in_sizes, int n_in,
                              void* d_out, int out_size) {
    const float* x     = (const float*)d_in[0];
    const int*   ei    = (const int*)d_in[1];
    const float* fcW   = (const float*)d_in[3];
    const float* fcb   = (const float*)d_in[4];
    const float* lin_l = (const float*)d_in[5];
    const float* lin_r = (const float*)d_in[6];
    const float* lin_b = (const float*)d_in[7];
    const float* ln_g  = (const float*)d_in[8];
    const float* ln_b  = (const float*)d_in[9];
    const int* src = ei;
    const int* dst = ei + N_EDGES;

    cudaFuncSetAttribute(k_gemm, cudaFuncAttributeMaxDynamicSharedMemorySize, GEMM_SMEM);

    // fused: fc GEMM (blocks 0..390) + edge count/rank (blocks 391..1953)
    k_gemm<<<GBLOCKS + CBLOCKS, 256, GEMM_SMEM>>>(x, 0, fcW, nullptr, fcb,
                                                  nullptr, nullptr, 0, 0, nullptr, dst);
    k_scan<<<NCHUNK, 512>>>();
    k_scatter<<<CBLOCKS, 256>>>(src, dst);

    int cur = 0;
    for (int l = 0; l < NUM_LAYERS; l++) {
        k_aggregate<<<(N_NODES * 32 + 255) / 256, 256>>>(cur);
        int mode = (l < NUM_LAYERS - 1) ? 1 : 2;
        k_gemm<<<GBLOCKS, 256, GEMM_SMEM>>>(nullptr, cur,
                                            lin_l + l * HID * HID,
                                            lin_r + l * HID * HID,
                                            lin_b + l * HID,
                                            ln_g + l * HID, ln_b + l * HID,
                                            mode, 1 - cur, (float*)d_out, nullptr);
        cur = 1 - cur;
    }
}

// round 14
// speedup vs baseline: 1.5508x; 1.0568x over previous
#include <cuda_runtime.h>
#include <cuda_fp16.h>
#include <cstdint>

#define N_NODES 50000
#define N_EDGES 1600000
#define IN_DIM 128
#define HID 64
#define NUM_LAYERS 3
#define LN_EPS 1e-5f
#define NCHUNK ((N_NODES + 511) / 512)   // 98
#define GBLOCKS ((N_NODES + 127) / 128)  // 391
#define CBLOCKS ((N_EDGES / 4 + 255) / 256)  // 1563

// GEMM: 128 rows x 64 cols per block, 256 threads, K processed in 2 phases of 64
#define STRIDE 72   // halfs per staged row (64 + 8 pad)
#define GEMM_SMEM ((128 * STRIDE * 2 + 64 * STRIDE * 2) * 2)   // 55296 B

// ---------------- scratch (device globals) ----------------------------------
__device__ __half g_hiA[N_NODES * HID];
__device__ __half g_loA[N_NODES * HID];
__device__ __half g_hiB[N_NODES * HID];
__device__ __half g_loB[N_NODES * HID];
__device__ __half g_aggHi[N_NODES * HID];
__device__ __half g_aggLo[N_NODES * HID];
__device__ int    g_cnt[N_NODES];        // zero at entry (zero-init / re-zeroed by final GEMM)
__device__ int    g_row[N_NODES];
__device__ float  g_invdeg[N_NODES];
__device__ int    g_rank[N_EDGES];
__device__ int    g_esrc[N_EDGES];

__device__ __forceinline__ __half* hibuf(int s) { return s == 0 ? g_hiA : g_hiB; }
__device__ __forceinline__ __half* lobuf(int s) { return s == 0 ? g_loA : g_loB; }

__device__ __forceinline__ uint32_t h2u(__half2 h) {
    return *reinterpret_cast<uint32_t*>(&h);
}
// split 8 fp32 into hi/lo fp16 packs
__device__ __forceinline__ void split8(const float* v, uint4& hi, uint4& lo) {
    __half h[8];
    __half l[8];
#pragma unroll
    for (int i = 0; i < 8; i++) {
        h[i] = __float2half_rn(v[i]);
        l[i] = __float2half_rn(v[i] - __half2float(h[i]));
    }
    hi.x = h2u(__halves2half2(h[0], h[1]));
    hi.y = h2u(__halves2half2(h[2], h[3]));
    hi.z = h2u(__halves2half2(h[4], h[5]));
    hi.w = h2u(__halves2half2(h[6], h[7]));
    lo.x = h2u(__halves2half2(l[0], l[1]));
    lo.y = h2u(__halves2half2(l[2], l[3]));
    lo.z = h2u(__halves2half2(l[4], l[5]));
    lo.w = h2u(__halves2half2(l[6], l[7]));
}

// ---------------- merged scan: base-reduce + chunk scan ----------------------
__global__ void k_scan() {
    __shared__ int red[512];
    __shared__ int s[512];
    int c = blockIdx.x, t = threadIdx.x, i = c * 512 + t;
    int lim = c * 512;
    int acc = 0;
    for (int j = t; j < lim; j += 512) acc += g_cnt[j];
    red[t] = acc;
    __syncthreads();
    for (int off = 256; off; off >>= 1) {
        if (t < off) red[t] += red[t + off];
        __syncthreads();
    }
    int base = red[0];
    int v = (i < N_NODES) ? g_cnt[i] : 0;
    s[t] = v;
    __syncthreads();
    for (int off = 1; off < 512; off <<= 1) {
        int x = (t >= off) ? s[t - off] : 0;
        __syncthreads();
        s[t] += x;
        __syncthreads();
    }
    if (i < N_NODES) {
        g_row[i] = base + s[t] - v;   // exclusive prefix
        g_invdeg[i] = 1.0f / (float)(v > 0 ? v : 1);
    }
}

// scatter with precomputed ranks — no atomics
__global__ void k_scatter(const int* __restrict__ src, const int* __restrict__ dst) {
    int i = blockIdx.x * blockDim.x + threadIdx.x;
    if (i < N_EDGES / 4) {
        int4 sv = ((const int4*)src)[i];
        int4 dv = ((const int4*)dst)[i];
        int4 rv = ((const int4*)g_rank)[i];
        g_esrc[g_row[dv.x] + rv.x] = sv.x;
        g_esrc[g_row[dv.y] + rv.y] = sv.y;
        g_esrc[g_row[dv.z] + rv.z] = sv.z;
        g_esrc[g_row[dv.w] + rv.w] = sv.w;
    }
}

// ---------------- mean aggregation (warp per dst node, issue-optimized) ------
// quarter-warp per neighbor: 8 lanes x uint4 (16 B) cover a 128 B row.
// Unroll 2 groups of 4 neighbors; HADD2 pairs them in fp16 before fp32 accum.
__global__ void k_aggregate(int hsel) {
    int gw = (blockIdx.x * blockDim.x + threadIdx.x) >> 5;
    if (gw >= N_NODES) return;
    int lane = threadIdx.x & 31;
    int qw = lane >> 3;          // quarter-warp 0..3 -> neighbor slot
    int fl = lane & 7;           // 16 B chunk index within row
    const uint4* hp = (const uint4*)hibuf(hsel);   // 8 uint4 per row
    int s = g_row[gw], c = g_cnt[gw];
    float f[8];
#pragma unroll
    for (int i = 0; i < 8; i++) f[i] = 0.f;

    int e = 0;
#pragma unroll 1
    for (; e + 8 <= c; e += 8) {
        int na = g_esrc[s + e + qw];
        int nb = g_esrc[s + e + 4 + qw];
        uint4 va = hp[(size_t)na * 8 + fl];
        uint4 vb = hp[(size_t)nb * 8 + fl];
        __half2 p0 = __hadd2(*(__half2*)&va.x, *(__half2*)&vb.x);
        __half2 p1 = __hadd2(*(__half2*)&va.y, *(__half2*)&vb.y);
        __half2 p2 = __hadd2(*(__half2*)&va.z, *(__half2*)&vb.z);
        __half2 p3 = __hadd2(*(__half2*)&va.w, *(__half2*)&vb.w);
        float2 q0 = __half22float2(p0), q1 = __half22float2(p1);
        float2 q2 = __half22float2(p2), q3 = __half22float2(p3);
        f[0] += q0.x; f[1] += q0.y; f[2] += q1.x; f[3] += q1.y;
        f[4] += q2.x; f[5] += q2.y; f[6] += q3.x; f[7] += q3.y;
    }
    // remainder: quarter-warp qw takes neighbors e+qw, e+qw+4, ...
#pragma unroll 1
    for (int e2 = e + qw; e2 < c; e2 += 4) {
        int n0 = g_esrc[s + e2];
        uint4 v = hp[(size_t)n0 * 8 + fl];
        float2 q0 = __half22float2(*(__half2*)&v.x);
        float2 q1 = __half22float2(*(__half2*)&v.y);
        float2 q2 = __half22float2(*(__half2*)&v.z);
        float2 q3 = __half22float2(*(__half2*)&v.w);
        f[0] += q0.x; f[1] += q0.y; f[2] += q1.x; f[3] += q1.y;
        f[4] += q2.x; f[5] += q2.y; f[6] += q3.x; f[7] += q3.y;
    }

    // reduce across quarter-warps (lanes fl, fl+8, fl+16, fl+24)
#pragma unroll
    for (int i = 0; i < 8; i++) {
        f[i] += __shfl_xor_sync(0xffffffffu, f[i], 8);
        f[i] += __shfl_xor_sync(0xffffffffu, f[i], 16);
    }

    if (qw == 0) {
        float id = g_invdeg[gw];
        float m[8];
#pragma unroll
        for (int i = 0; i < 8; i++) m[i] = f[i] * id;
        uint4 dh, dl;
        split8(m, dh, dl);
        ((uint4*)g_aggHi)[(size_t)gw * 8 + fl] = dh;
        ((uint4*)g_aggLo)[(size_t)gw * 8 + fl] = dl;
    }
}

// ---------------- split-fp16 HMMA GEMM (two K-phases of 64) ------------------
// mode: 0 = ReLU -> h(outsel); 1 = LN+ReLU -> h(outsel); 2 = raw -> outF (+zero g_cnt)
// dstE non-null (fc call only): blocks >= GBLOCKS run the edge histogram+rank.
__global__ void k_gemm(const float* __restrict__ xA0, int hsel,
                       const float* __restrict__ W0, const float* __restrict__ W1,
                       const float* __restrict__ bias,
                       const float* __restrict__ lng, const float* __restrict__ lnbeta,
                       int mode, int outsel, float* __restrict__ outF,
                       const int* __restrict__ dstE) {
    if (dstE != nullptr && blockIdx.x >= GBLOCKS) {
        int i = (blockIdx.x - GBLOCKS) * blockDim.x + threadIdx.x;
        if (i < N_EDGES / 4) {
            int4 d = ((const int4*)dstE)[i];
            int4 r;
            r.x = atomicAdd(&g_cnt[d.x], 1);
            r.y = atomicAdd(&g_cnt[d.y], 1);
            r.z = atomicAdd(&g_cnt[d.z], 1);
            r.w = atomicAdd(&g_cnt[d.w], 1);
            ((int4*)g_rank)[i] = r;
        }
        return;
    }

    extern __shared__ __half sm[];
    __half* sAh = sm;                    // [128][STRIDE]
    __half* sAl = sm + 128 * STRIDE;
    __half* sBh = sm + 256 * STRIDE;     // [64][STRIDE]
    __half* sBl = sm + 320 * STRIDE;

    int t = threadIdx.x;
    int nb = blockIdx.x * 128;
    int warp = t >> 5, lane = t & 31;
    int wm = warp * 16;
    const __half* hHi = hibuf(hsel);
    const __half* hLo = lobuf(hsel);

    float acc[8][4];
#pragma unroll
    for (int p = 0; p < 8; p++)
#pragma unroll
        for (int q = 0; q < 4; q++) acc[p][q] = 0.f;

    uint32_t aOff = (uint32_t)((wm + (lane & 15)) * STRIDE + (lane >> 4) * 8) * 2;
    uint32_t aShH = (uint32_t)__cvta_generic_to_shared(sAh) + aOff;
    uint32_t aShL = (uint32_t)__cvta_generic_to_shared(sAl) + aOff;
    int ng = lane >> 3;
    int bRow = ((ng >> 1) * 8) + (lane & 7);
    int bK = (ng & 1) * 8;
    uint32_t bShH = (uint32_t)__cvta_generic_to_shared(sBh);
    uint32_t bShL = (uint32_t)__cvta_generic_to_shared(sBl);

#define LDM(r0, r1, r2, r3, addr) \
    asm volatile("ldmatrix.sync.aligned.m8n8.x4.shared.b16 {%0,%1,%2,%3}, [%4];" \
                 : "=r"(r0), "=r"(r1), "=r"(r2), "=r"(r3) : "r"(addr))
#define MMA(accp, x0, x1, x2, x3, y0, y1) \
    asm volatile("mma.sync.aligned.m16n8k16.row.col.f32.f16.f16.f32 " \
                 "{%0,%1,%2,%3}, {%4,%5,%6,%7}, {%8,%9}, {%0,%1,%2,%3};" \
                 : "+f"(accp[0]), "+f"(accp[1]), "+f"(accp[2]), "+f"(accp[3]) \
                 : "r"(x0), "r"(x1), "r"(x2), "r"(x3), "r"(y0), "r"(y1))

#pragma unroll 1
    for (int ph = 0; ph < 2; ph++) {
        // ---- stage B tile for this phase ----
#pragma unroll
        for (int it = 0; it < 2; it++) {
            int idx = it * 256 + t;            // 512 slots
            int j = idx >> 3, k8 = idx & 7;
            float v[8];
            if (xA0) {
                *(float4*)&v[0] = ((const float4*)W0)[j * 32 + ph * 16 + k8 * 2];
                *(float4*)&v[4] = ((const float4*)W0)[j * 32 + ph * 16 + k8 * 2 + 1];
            } else {
                const float* Wp = ph ? W1 : W0;
                *(float4*)&v[0] = ((const float4*)Wp)[j * 16 + k8 * 2];
                *(float4*)&v[4] = ((const float4*)Wp)[j * 16 + k8 * 2 + 1];
            }
            uint4 dh, dl;
            split8(v, dh, dl);
            *(uint4*)&sBh[j * STRIDE + k8 * 8] = dh;
            *(uint4*)&sBl[j * STRIDE + k8 * 8] = dl;
        }

        // ---- stage A tile for this phase ----
#pragma unroll
        for (int it = 0; it < 4; it++) {
            int idx = it * 256 + t;            // 1024 slots
            int n = idx >> 3, k8 = idx & 7;
            int gn = nb + n;
            uint4 dh = make_uint4(0u, 0u, 0u, 0u), dl = dh;
            if (gn < N_NODES) {
                if (xA0) {
                    float v[8];
                    *(float4*)&v[0] = ((const float4*)xA0)[(size_t)gn * 32 + ph * 16 + k8 * 2];
                    *(float4*)&v[4] = ((const float4*)xA0)[(size_t)gn * 32 + ph * 16 + k8 * 2 + 1];
                    split8(v, dh, dl);
                } else if (ph == 0) {
                    dh = ((const uint4*)g_aggHi)[(size_t)gn * 8 + k8];
                    dl = ((const uint4*)g_aggLo)[(size_t)gn * 8 + k8];
                } else {
                    dh = ((const uint4*)hHi)[(size_t)gn * 8 + k8];
                    dl = ((const uint4*)hLo)[(size_t)gn * 8 + k8];
                }
            }
            *(uint4*)&sAh[n * STRIDE + k8 * 8] = dh;
            *(uint4*)&sAl[n * STRIDE + k8 * 8] = dl;
        }
        __syncthreads();

        // ---- MMA over this K phase ----
#pragma unroll
        for (int kk = 0; kk < 4; kk++) {
            uint32_t ah0, ah1, ah2, ah3, al0, al1, al2, al3;
            LDM(ah0, ah1, ah2, ah3, aShH + kk * 32);
            LDM(al0, al1, al2, al3, aShL + kk * 32);
#pragma unroll
            for (int tp = 0; tp < 4; tp++) {
                uint32_t bOff = (uint32_t)((tp * 16 + bRow) * STRIDE + kk * 16 + bK) * 2;
                uint32_t bh0, bh1, bh2, bh3, bl0, bl1, bl2, bl3;
                LDM(bh0, bh1, bh2, bh3, bShH + bOff);
                LDM(bl0, bl1, bl2, bl3, bShL + bOff);
                MMA(acc[2 * tp],     ah0, ah1, ah2, ah3, bh0, bh1);
                MMA(acc[2 * tp],     ah0, ah1, ah2, ah3, bl0, bl1);
                MMA(acc[2 * tp],     al0, al1, al2, al3, bh0, bh1);
                MMA(acc[2 * tp + 1], ah0, ah1, ah2, ah3, bh2, bh3);
                MMA(acc[2 * tp + 1], ah0, ah1, ah2, ah3, bl2, bl3);
                MMA(acc[2 * tp + 1], al0, al1, al2, al3, bh2, bh3);
            }
        }
        __syncthreads();
    }
#undef LDM
#undef MMA

    // ---- epilogue: bias (+LN) (+ReLU), write from registers ----
    int r = lane >> 2, cc = (lane & 3) * 2;
#pragma unroll
    for (int p = 0; p < 8; p++) {
        float b0 = __ldg(&bias[p * 8 + cc]);
        float b1 = __ldg(&bias[p * 8 + cc + 1]);
        acc[p][0] += b0; acc[p][1] += b1;
        acc[p][2] += b0; acc[p][3] += b1;
    }
    if (mode == 1) {
        float s0 = 0.f, q0 = 0.f, s1 = 0.f, q1 = 0.f;
#pragma unroll
        for (int p = 0; p < 8; p++) {
            s0 += acc[p][0] + acc[p][1];
            q0 += acc[p][0] * acc[p][0] + acc[p][1] * acc[p][1];
            s1 += acc[p][2] + acc[p][3];
            q1 += acc[p][2] * acc[p][2] + acc[p][3] * acc[p][3];
        }
#pragma unroll
        for (int off = 1; off < 4; off <<= 1) {
            s0 += __shfl_xor_sync(0xffffffffu, s0, off);
            q0 += __shfl_xor_sync(0xffffffffu, q0, off);
            s1 += __shfl_xor_sync(0xffffffffu, s1, off);
            q1 += __shfl_xor_sync(0xffffffffu, q1, off);
        }
        float mu0 = s0 * (1.0f / HID), mu1 = s1 * (1.0f / HID);
        float rs0 = rsqrtf(q0 * (1.0f / HID) - mu0 * mu0 + LN_EPS);
        float rs1 = rsqrtf(q1 * (1.0f / HID) - mu1 * mu1 + LN_EPS);
#pragma unroll
        for (int p = 0; p < 8; p++) {
            float g0 = __ldg(&lng[p * 8 + cc]);
            float g1 = __ldg(&lng[p * 8 + cc + 1]);
            float t0 = __ldg(&lnbeta[p * 8 + cc]);
            float t1 = __ldg(&lnbeta[p * 8 + cc + 1]);
            acc[p][0] = fmaxf(fmaf(g0, (acc[p][0] - mu0) * rs0, t0), 0.f);
            acc[p][1] = fmaxf(fmaf(g1, (acc[p][1] - mu0) * rs0, t1), 0.f);
            acc[p][2] = fmaxf(fmaf(g0, (acc[p][2] - mu1) * rs1, t0), 0.f);
            acc[p][3] = fmaxf(fmaf(g1, (acc[p][3] - mu1) * rs1, t1), 0.f);
        }
    } else if (mode == 0) {
#pragma unroll
        for (int p = 0; p < 8; p++)
#pragma unroll
            for (int q = 0; q < 4; q++) acc[p][q] = fmaxf(acc[p][q], 0.f);
    }

    int gn0 = nb + wm + r, gn1 = gn0 + 8;
    if (mode == 2) {
#pragma unroll
        for (int p = 0; p < 8; p++) {
            int ci = p * 4 + (lane & 3);
            if (gn0 < N_NODES)
                ((float2*)outF)[(size_t)gn0 * 32 + ci] = make_float2(acc[p][0], acc[p][1]);
            if (gn1 < N_NODES)
                ((float2*)outF)[(size_t)gn1 * 32 + ci] = make_float2(acc[p][2], acc[p][3]);
        }
        // restore g_cnt = 0 for the next graph replay
        if (t < 128) {
            int zi = blockIdx.x * 128 + t;
            if (zi < N_NODES) g_cnt[zi] = 0;
        }
    } else {
        __half2* oHi = (__half2*)hibuf(outsel);
        __half2* oLo = (__half2*)lobuf(outsel);
#pragma unroll
        for (int p = 0; p < 8; p++) {
            int ci = p * 4 + (lane & 3);
            if (gn0 < N_NODES) {
                __half h0 = __float2half_rn(acc[p][0]);
                __half h1 = __float2half_rn(acc[p][1]);
                oHi[(size_t)gn0 * 32 + ci] = __halves2half2(h0, h1);
                oLo[(size_t)gn0 * 32 + ci] = __halves2half2(
                    __float2half_rn(acc[p][0] - __half2float(h0)),
                    __float2half_rn(acc[p][1] - __half2float(h1)));
            }
            if (gn1 < N_NODES) {
                __half h2 = __float2half_rn(acc[p][2]);
                __half h3 = __float2half_rn(acc[p][3]);
                oHi[(size_t)gn1 * 32 + ci] = __halves2half2(h2, h3);
                oLo[(size_t)gn1 * 32 + ci] = __halves2half2(
                    __float2half_rn(acc[p][2] - __half2float(h2)),
                    __float2half_rn(acc[p][3] - __half2float(h3)));
            }
        }
    }
}

// ---------------- launcher ---------------------------------------------------
extern "C" void kernel_launch(void* const* d_in, const int* in_sizes, int n_in,
                              void* d_out, int out_size) {
    const float* x     = (const float*)d_in[0];
    const int*   ei    = (const int*)d_in[1];
    const float* fcW   = (const float*)d_in[3];
    const float* fcb   = (const float*)d_in[4];
    const float* lin_l = (const float*)d_in[5];
    const float* lin_r = (const float*)d_in[6];
    const float* lin_b = (const float*)d_in[7];
    const float* ln_g  = (const float*)d_in[8];
    const float* ln_b  = (const float*)d_in[9];
    const int* src = ei;
    const int* dst = ei + N_EDGES;

    cudaFuncSetAttribute(k_gemm, cudaFuncAttributeMaxDynamicSharedMemorySize, GEMM_SMEM);

    // fused: fc GEMM (blocks 0..390) + edge count/rank (blocks 391..1953)
    k_gemm<<<GBLOCKS + CBLOCKS, 256, GEMM_SMEM>>>(x, 0, fcW, nullptr, fcb,
                                                  nullptr, nullptr, 0, 0, nullptr, dst);
    k_scan<<<NCHUNK, 512>>>();
    k_scatter<<<CBLOCKS, 256>>>(src, dst);

    int cur = 0;
    for (int l = 0; l < NUM_LAYERS; l++) {
        k_aggregate<<<(N_NODES * 32 + 255) / 256, 256>>>(cur);
        int mode = (l < NUM_LAYERS - 1) ? 1 : 2;
        k_gemm<<<GBLOCKS, 256, GEMM_SMEM>>>(nullptr, cur,
                                            lin_l + l * HID * HID,
                                            lin_r + l * HID * HID,
                                            lin_b + l * HID,
                                            ln_g + l * HID, ln_b + l * HID,
                                            mode, 1 - cur, (float*)d_out, nullptr);
        cur = 1 - cur;
    }
}